// round 2
// baseline (speedup 1.0000x reference)
#include <cuda_runtime.h>
#include <math.h>

#define B_ 2
#define S_ 2048
#define E_ 1024
#define H_ 16
#define D_ 64

// Scratch (allocation-free rule: __device__ globals)
__device__ float g_Q[B_ * S_ * E_];
__device__ float g_K[B_ * S_ * E_];
__device__ float g_V[B_ * S_ * E_];
__device__ float g_C[B_ * S_ * E_];

// ============================================================================
// SGEMM (NT): C[M,N] = A[M,K] @ W[N,K]^T + bias[N]
// 128x128 tile, BK=8, 256 threads, 8x8 register micro-tile.
// ============================================================================
#define GBM 128
#define GBN 128
#define GBK 8
#define GTM 8
#define GTN 8
#define GPAD 4

__global__ __launch_bounds__(256)
void sgemm_nt_bias(const float* __restrict__ A, const float* __restrict__ W,
                   const float* __restrict__ bias, float* __restrict__ C,
                   int M, int N, int K) {
    __shared__ float As[GBK][GBM + GPAD];
    __shared__ float Ws[GBK][GBN + GPAD];

    const int tid = threadIdx.x;
    const int tx = tid % 16;          // column group
    const int ty = tid / 16;          // row group
    const int bm = blockIdx.y * GBM;
    const int bn = blockIdx.x * GBN;

    // Load mapping: each thread loads one float4 from A and one from W per k-tile.
    const int lrow = tid >> 1;              // 0..127
    const int lk   = (tid & 1) * 4;         // 0 or 4
    const float* Ap = A + (size_t)(bm + lrow) * K + lk;
    const float* Wp = W + (size_t)(bn + lrow) * K + lk;

    float acc[GTM][GTN];
#pragma unroll
    for (int i = 0; i < GTM; i++)
#pragma unroll
        for (int j = 0; j < GTN; j++) acc[i][j] = 0.0f;

    for (int k0 = 0; k0 < K; k0 += GBK) {
        float4 av = *(const float4*)(Ap + k0);
        float4 wv = *(const float4*)(Wp + k0);
        __syncthreads();   // protect previous tile reads
        As[lk + 0][lrow] = av.x; As[lk + 1][lrow] = av.y;
        As[lk + 2][lrow] = av.z; As[lk + 3][lrow] = av.w;
        Ws[lk + 0][lrow] = wv.x; Ws[lk + 1][lrow] = wv.y;
        Ws[lk + 2][lrow] = wv.z; Ws[lk + 3][lrow] = wv.w;
        __syncthreads();

#pragma unroll
        for (int kk = 0; kk < GBK; kk++) {
            float a[GTM], w[GTN];
            *(float4*)&a[0] = *(const float4*)&As[kk][ty * GTM];
            *(float4*)&a[4] = *(const float4*)&As[kk][ty * GTM + 4];
            *(float4*)&w[0] = *(const float4*)&Ws[kk][tx * GTN];
            *(float4*)&w[4] = *(const float4*)&Ws[kk][tx * GTN + 4];
#pragma unroll
            for (int i = 0; i < GTM; i++)
#pragma unroll
                for (int j = 0; j < GTN; j++)
                    acc[i][j] = fmaf(a[i], w[j], acc[i][j]);
        }
    }

    // Epilogue: add bias, store.
#pragma unroll
    for (int i = 0; i < GTM; i++) {
        const int row = bm + ty * GTM + i;
        float* Cp = C + (size_t)row * N + bn + tx * GTN;
#pragma unroll
        for (int j = 0; j < GTN; j++)
            Cp[j] = acc[i][j] + bias[bn + tx * GTN + j];
    }
}

// ============================================================================
// Flash attention (fp32, causal). One query row per thread.
// Layout: Q/K/V/C are [B*S, E] with head h at column offset h*D (stride E).
// grid = (S/128, H, B), block = 128 threads.
// ============================================================================
#define AT_ROWS 128
#define AT_TC 16

__global__ __launch_bounds__(AT_ROWS)
void flash_attn_causal(const float* __restrict__ Q, const float* __restrict__ K,
                       const float* __restrict__ V, float* __restrict__ O) {
    const int b = blockIdx.z;
    const int h = blockIdx.y;
    const int r = blockIdx.x * AT_ROWS + threadIdx.x;   // query row within sequence

    __shared__ float Ks[AT_TC][D_];
    __shared__ float Vs[AT_TC][D_];

    // Load q row into registers, pre-scaled by 1/sqrt(D)
    const float* Qp = Q + ((size_t)b * S_ + r) * E_ + h * D_;
    float q[D_];
#pragma unroll
    for (int d = 0; d < D_; d++) q[d] = Qp[d] * 0.125f;

    float o[D_];
#pragma unroll
    for (int d = 0; d < D_; d++) o[d] = 0.0f;
    float mx = -1e30f;
    float l = 0.0f;

    const int jmax = blockIdx.x * AT_ROWS + AT_ROWS;  // causal: keys < jmax

    for (int j0 = 0; j0 < jmax; j0 += AT_TC) {
        __syncthreads();
        // Stage K/V tile: AT_TC x 64 floats = 256 float4, 128 threads -> 2 each
#pragma unroll
        for (int t = threadIdx.x; t < AT_TC * (D_ / 4); t += AT_ROWS) {
            const int jj = t >> 4;            // D_/4 = 16 float4 per row
            const int dd = (t & 15) * 4;
            const size_t src = ((size_t)b * S_ + j0 + jj) * E_ + h * D_ + dd;
            *(float4*)&Ks[jj][dd] = *(const float4*)(K + src);
            *(float4*)&Vs[jj][dd] = *(const float4*)(V + src);
        }
        __syncthreads();

        // Scores for this tile
        float s[AT_TC];
        float tmax = mx;
#pragma unroll
        for (int jj = 0; jj < AT_TC; jj++) {
            float a0 = 0.f, a1 = 0.f, a2 = 0.f, a3 = 0.f;
#pragma unroll
            for (int d = 0; d < D_; d += 4) {
                float4 kv = *(const float4*)&Ks[jj][d];
                a0 = fmaf(q[d + 0], kv.x, a0);
                a1 = fmaf(q[d + 1], kv.y, a1);
                a2 = fmaf(q[d + 2], kv.z, a2);
                a3 = fmaf(q[d + 3], kv.w, a3);
            }
            const float sc = (a0 + a1) + (a2 + a3);
            s[jj] = (j0 + jj <= r) ? sc : -1e30f;
            tmax = fmaxf(tmax, s[jj]);
        }

        // Online softmax correction (once per tile)
        const float corr = __expf(mx - tmax);
        mx = tmax;
        l *= corr;
#pragma unroll
        for (int d = 0; d < D_; d++) o[d] *= corr;

        // Accumulate
#pragma unroll
        for (int jj = 0; jj < AT_TC; jj++) {
            const float p = __expf(s[jj] - mx);
            l += p;
#pragma unroll
            for (int d = 0; d < D_; d += 4) {
                float4 vv = *(const float4*)&Vs[jj][d];
                o[d + 0] = fmaf(p, vv.x, o[d + 0]);
                o[d + 1] = fmaf(p, vv.y, o[d + 1]);
                o[d + 2] = fmaf(p, vv.z, o[d + 2]);
                o[d + 3] = fmaf(p, vv.w, o[d + 3]);
            }
        }
    }

    const float inv = 1.0f / l;
    float* Op = O + ((size_t)b * S_ + r) * E_ + h * D_;
#pragma unroll
    for (int d = 0; d < D_; d++) Op[d] = o[d] * inv;
}

// ============================================================================
// Launch
// ============================================================================
extern "C" void kernel_launch(void* const* d_in, const int* in_sizes, int n_in,
                              void* d_out, int out_size) {
    (void)in_sizes; (void)n_in; (void)out_size;

    const float* q  = (const float*)d_in[0];
    const float* k  = (const float*)d_in[1];
    const float* v  = (const float*)d_in[2];
    // d_in[3] = mask (causal tril) — handled analytically in the attention kernel
    const float* Wq = (const float*)d_in[4];
    const float* bq = (const float*)d_in[5];
    const float* Wk = (const float*)d_in[6];
    const float* bk = (const float*)d_in[7];
    const float* Wv = (const float*)d_in[8];
    const float* bv = (const float*)d_in[9];
    const float* Wo = (const float*)d_in[10];
    const float* bo = (const float*)d_in[11];
    float* out = (float*)d_out;

    float *pQ, *pK, *pV, *pC;
    cudaGetSymbolAddress((void**)&pQ, g_Q);
    cudaGetSymbolAddress((void**)&pK, g_K);
    cudaGetSymbolAddress((void**)&pV, g_V);
    cudaGetSymbolAddress((void**)&pC, g_C);

    const int M = B_ * S_;   // 4096
    const int N = E_;        // 1024
    const int K = E_;        // 1024

    dim3 ggrid(N / GBN, M / GBM);   // (8, 32)
    dim3 gblk(256);

    sgemm_nt_bias<<<ggrid, gblk>>>(q, Wq, bq, pQ, M, N, K);
    sgemm_nt_bias<<<ggrid, gblk>>>(k, Wk, bk, pK, M, N, K);
    sgemm_nt_bias<<<ggrid, gblk>>>(v, Wv, bv, pV, M, N, K);

    dim3 agrid(S_ / AT_ROWS, H_, B_);   // (16, 16, 2)
    flash_attn_causal<<<agrid, AT_ROWS>>>(pQ, pK, pV, pC);

    sgemm_nt_bias<<<ggrid, gblk>>>(pC, Wo, bo, out, M, N, K);
}

// round 4
// speedup vs baseline: 1.3719x; 1.3719x over previous
#include <cuda_runtime.h>
#include <cuda_bf16.h>
#include <math.h>

#define B_ 2
#define S_ 2048
#define E_ 1024
#define H_ 16
#define D_ 64

// Scratch (allocation-free rule: __device__ globals)
__device__ float g_Q[B_ * S_ * E_];
__device__ float g_K[B_ * S_ * E_];
__device__ float g_V[B_ * S_ * E_];
__device__ float g_C[B_ * S_ * E_];

// ============================================================================
// Helpers
// ============================================================================
__device__ __forceinline__ unsigned smem_u32(const void* p) {
    unsigned a;
    asm("{ .reg .u64 t; cvta.to.shared.u64 t, %1; cvt.u32.u64 %0, t; }"
        : "=r"(a) : "l"(p));
    return a;
}

#define STS128(r0, r1, r2, r3, sa) \
    asm volatile("st.shared.v4.b32 [%0], {%1, %2, %3, %4};" \
                 :: "r"(sa), "r"(r0), "r"(r1), "r"(r2), "r"(r3) : "memory")

__device__ __forceinline__ void ldsm4(unsigned* r, unsigned addr) {
    asm volatile("ldmatrix.sync.aligned.m8n8.x4.shared.b16 {%0,%1,%2,%3}, [%4];"
                 : "=r"(r[0]), "=r"(r[1]), "=r"(r[2]), "=r"(r[3]) : "r"(addr));
}

__device__ __forceinline__ void mma16816(float* d, const unsigned* a,
                                         unsigned b0, unsigned b1) {
    asm volatile(
        "mma.sync.aligned.m16n8k16.row.col.f32.bf16.bf16.f32 "
        "{%0,%1,%2,%3}, {%4,%5,%6,%7}, {%8,%9}, {%0,%1,%2,%3};"
        : "+f"(d[0]), "+f"(d[1]), "+f"(d[2]), "+f"(d[3])
        : "r"(a[0]), "r"(a[1]), "r"(a[2]), "r"(a[3]), "r"(b0), "r"(b1));
}

// pack two fp32 -> bf16x2 (low half = first arg)
__device__ __forceinline__ unsigned pack_bf2(float flo, float fhi) {
    unsigned r;
    asm("cvt.rn.bf16x2.f32 %0, %1, %2;" : "=r"(r) : "f"(fhi), "f"(flo));
    return r;
}
// x = hi(bf16) + lo(bf16) split, packed pairs
__device__ __forceinline__ void split2(float x0, float x1, unsigned& hi, unsigned& lo) {
    hi = pack_bf2(x0, x1);
    float h0 = __uint_as_float(hi << 16);
    float h1 = __uint_as_float(hi & 0xFFFF0000u);
    lo = pack_bf2(x0 - h0, x1 - h1);
}

// ============================================================================
// GEMM (NT): C[M,N] = A[M,K] @ W[N,K]^T + bias[N]   via mma.sync bf16 split.
// Block 128x128, BK=32, 256 threads (8 warps, each 32m x 64n).
// smem tile piece: 128 rows x 64B (32 bf16), XOR swizzle chunk^=(row>>1)&3.
// Stage layout: [Ahi | Alo | Whi | Wlo] x 2 stages = 64KB.
// ============================================================================
#define PIECE 8192
#define STG_BYTES (4 * PIECE)
#define GM_DSMEM (2 * STG_BYTES)

__global__ __launch_bounds__(256)
void gemm_mma(const float* __restrict__ A, const float* __restrict__ W,
              const float* __restrict__ bias, float* __restrict__ C,
              int M, int N, int K) {
    extern __shared__ char smem_raw[];
    const unsigned sbase = smem_u32(smem_raw);
    const int tid = threadIdx.x;
    const int lane = tid & 31;
    const int wid = tid >> 5;
    const int bm = blockIdx.y * 128;
    const int bn = blockIdx.x * 128;

    // ---- staging mapping: thread -> (row, 16-float half of BK=32) ----
    const int srow = tid >> 1;
    const int sseg = tid & 1;
    const float* Ap = A + (size_t)(bm + srow) * K + sseg * 16;
    const float* Wp = W + (size_t)(bn + srow) * K + sseg * 16;
    const unsigned sg = (srow >> 1) & 3;
    const unsigned st0 = (unsigned)(srow * 64) + ((((unsigned)sseg * 2 + 0) ^ sg) << 4);
    const unsigned st1 = (unsigned)(srow * 64) + ((((unsigned)sseg * 2 + 1) ^ sg) << 4);

    float4 ra0, ra1, ra2, ra3, rw0, rw1, rw2, rw3;

    auto loadc = [&](int c) {
        const float* pa = Ap + c * 32;
        ra0 = *(const float4*)(pa);
        ra1 = *(const float4*)(pa + 4);
        ra2 = *(const float4*)(pa + 8);
        ra3 = *(const float4*)(pa + 12);
        const float* pw = Wp + c * 32;
        rw0 = *(const float4*)(pw);
        rw1 = *(const float4*)(pw + 4);
        rw2 = *(const float4*)(pw + 8);
        rw3 = *(const float4*)(pw + 12);
    };

    auto storec = [&](unsigned stg) {
        unsigned h[8], l[8];
        split2(ra0.x, ra0.y, h[0], l[0]); split2(ra0.z, ra0.w, h[1], l[1]);
        split2(ra1.x, ra1.y, h[2], l[2]); split2(ra1.z, ra1.w, h[3], l[3]);
        split2(ra2.x, ra2.y, h[4], l[4]); split2(ra2.z, ra2.w, h[5], l[5]);
        split2(ra3.x, ra3.y, h[6], l[6]); split2(ra3.z, ra3.w, h[7], l[7]);
        STS128(h[0], h[1], h[2], h[3], stg + st0);
        STS128(h[4], h[5], h[6], h[7], stg + st1);
        STS128(l[0], l[1], l[2], l[3], stg + PIECE + st0);
        STS128(l[4], l[5], l[6], l[7], stg + PIECE + st1);
        split2(rw0.x, rw0.y, h[0], l[0]); split2(rw0.z, rw0.w, h[1], l[1]);
        split2(rw1.x, rw1.y, h[2], l[2]); split2(rw1.z, rw1.w, h[3], l[3]);
        split2(rw2.x, rw2.y, h[4], l[4]); split2(rw2.z, rw2.w, h[5], l[5]);
        split2(rw3.x, rw3.y, h[6], l[6]); split2(rw3.z, rw3.w, h[7], l[7]);
        STS128(h[0], h[1], h[2], h[3], stg + 2 * PIECE + st0);
        STS128(h[4], h[5], h[6], h[7], stg + 2 * PIECE + st1);
        STS128(l[0], l[1], l[2], l[3], stg + 3 * PIECE + st0);
        STS128(l[4], l[5], l[6], l[7], stg + 3 * PIECE + st1);
    };

    // ---- compute mapping (per warp: 32m x 64n) ----
    const int wm = (wid & 3) * 32;
    const int wn = (wid >> 2) * 64;
    const unsigned aRow = (unsigned)((wm + (lane & 15)) * 64);
    const unsigned aG = (((unsigned)lane & 15) >> 1) & 3;
    const unsigned aHalf = (unsigned)lane >> 4;
    const unsigned bLocal = ((unsigned)lane & 7) + (((unsigned)lane & 16) >> 1);
    const unsigned bRow = (unsigned)((wn + (int)bLocal) * 64);
    const unsigned bG = (bLocal >> 1) & 3;
    const unsigned bHalf = ((unsigned)lane >> 3) & 1;

    float acc[2][8][4];
#pragma unroll
    for (int i = 0; i < 2; i++)
#pragma unroll
        for (int j = 0; j < 8; j++)
#pragma unroll
            for (int t = 0; t < 4; t++) acc[i][j][t] = 0.0f;

    auto compute = [&](unsigned stg) {
#pragma unroll
        for (int ks = 0; ks < 2; ks++) {
            unsigned ah0[4], ah1[4], al0[4], al1[4];
            const unsigned aoffs = (((unsigned)(2 * ks) + aHalf) ^ aG) << 4;
            ldsm4(ah0, stg + aRow + aoffs);
            ldsm4(ah1, stg + aRow + 1024 + aoffs);
            ldsm4(al0, stg + PIECE + aRow + aoffs);
            ldsm4(al1, stg + PIECE + aRow + 1024 + aoffs);
            const unsigned boffs = (((unsigned)(2 * ks) + bHalf) ^ bG) << 4;
#pragma unroll
            for (int ng = 0; ng < 4; ng++) {
                unsigned bh[4], bl[4];
                ldsm4(bh, stg + 2 * PIECE + bRow + ng * 1024 + boffs);
                ldsm4(bl, stg + 3 * PIECE + bRow + ng * 1024 + boffs);
                // hi*hi
                mma16816(acc[0][2 * ng],     ah0, bh[0], bh[1]);
                mma16816(acc[0][2 * ng + 1], ah0, bh[2], bh[3]);
                mma16816(acc[1][2 * ng],     ah1, bh[0], bh[1]);
                mma16816(acc[1][2 * ng + 1], ah1, bh[2], bh[3]);
                // hi*lo
                mma16816(acc[0][2 * ng],     ah0, bl[0], bl[1]);
                mma16816(acc[0][2 * ng + 1], ah0, bl[2], bl[3]);
                mma16816(acc[1][2 * ng],     ah1, bl[0], bl[1]);
                mma16816(acc[1][2 * ng + 1], ah1, bl[2], bl[3]);
                // lo*hi
                mma16816(acc[0][2 * ng],     al0, bh[0], bh[1]);
                mma16816(acc[0][2 * ng + 1], al0, bh[2], bh[3]);
                mma16816(acc[1][2 * ng],     al1, bh[0], bh[1]);
                mma16816(acc[1][2 * ng + 1], al1, bh[2], bh[3]);
            }
        }
    };

    const int nchunk = K / 32;
    loadc(0);
    storec(sbase);
    __syncthreads();
    for (int c = 0; c < nchunk; c++) {
        const unsigned stg = sbase + (unsigned)(c & 1) * STG_BYTES;
        if (c + 1 < nchunk) loadc(c + 1);
        compute(stg);
        if (c + 1 < nchunk) storec(sbase + (unsigned)((c + 1) & 1) * STG_BYTES);
        __syncthreads();
    }

    // ---- epilogue: bias add + store ----
    const int r0 = bm + wm + (lane >> 2);
    const int c0 = bn + wn + (lane & 3) * 2;
#pragma unroll
    for (int mf = 0; mf < 2; mf++) {
#pragma unroll
        for (int ng = 0; ng < 8; ng++) {
            const int row = r0 + mf * 16;
            const int col = c0 + ng * 8;
            const float2 bb = *(const float2*)(bias + col);
            float2 v0, v1;
            v0.x = acc[mf][ng][0] + bb.x;
            v0.y = acc[mf][ng][1] + bb.y;
            v1.x = acc[mf][ng][2] + bb.x;
            v1.y = acc[mf][ng][3] + bb.y;
            *(float2*)(C + (size_t)row * N + col) = v0;
            *(float2*)(C + (size_t)(row + 8) * N + col) = v1;
        }
    }
}

// ============================================================================
// Flash attention (fp32, causal). One query row per thread. (unchanged)
// ============================================================================
#define AT_ROWS 128
#define AT_TC 16

__global__ __launch_bounds__(AT_ROWS)
void flash_attn_causal(const float* __restrict__ Q, const float* __restrict__ K,
                       const float* __restrict__ V, float* __restrict__ O) {
    const int b = blockIdx.z;
    const int h = blockIdx.y;
    const int r = blockIdx.x * AT_ROWS + threadIdx.x;

    __shared__ float Ks[AT_TC][D_];
    __shared__ float Vs[AT_TC][D_];

    const float* Qp = Q + ((size_t)b * S_ + r) * E_ + h * D_;
    float q[D_];
#pragma unroll
    for (int d = 0; d < D_; d++) q[d] = Qp[d] * 0.125f;

    float o[D_];
#pragma unroll
    for (int d = 0; d < D_; d++) o[d] = 0.0f;
    float mx = -1e30f;
    float l = 0.0f;

    const int jmax = blockIdx.x * AT_ROWS + AT_ROWS;

    for (int j0 = 0; j0 < jmax; j0 += AT_TC) {
        __syncthreads();
#pragma unroll
        for (int t = threadIdx.x; t < AT_TC * (D_ / 4); t += AT_ROWS) {
            const int jj = t >> 4;
            const int dd = (t & 15) * 4;
            const size_t src = ((size_t)b * S_ + j0 + jj) * E_ + h * D_ + dd;
            *(float4*)&Ks[jj][dd] = *(const float4*)(K + src);
            *(float4*)&Vs[jj][dd] = *(const float4*)(V + src);
        }
        __syncthreads();

        float s[AT_TC];
        float tmax = mx;
#pragma unroll
        for (int jj = 0; jj < AT_TC; jj++) {
            float a0 = 0.f, a1 = 0.f, a2 = 0.f, a3 = 0.f;
#pragma unroll
            for (int d = 0; d < D_; d += 4) {
                float4 kv = *(const float4*)&Ks[jj][d];
                a0 = fmaf(q[d + 0], kv.x, a0);
                a1 = fmaf(q[d + 1], kv.y, a1);
                a2 = fmaf(q[d + 2], kv.z, a2);
                a3 = fmaf(q[d + 3], kv.w, a3);
            }
            const float sc = (a0 + a1) + (a2 + a3);
            s[jj] = (j0 + jj <= r) ? sc : -1e30f;
            tmax = fmaxf(tmax, s[jj]);
        }

        const float corr = __expf(mx - tmax);
        mx = tmax;
        l *= corr;
#pragma unroll
        for (int d = 0; d < D_; d++) o[d] *= corr;

#pragma unroll
        for (int jj = 0; jj < AT_TC; jj++) {
            const float p = __expf(s[jj] - mx);
            l += p;
#pragma unroll
            for (int d = 0; d < D_; d += 4) {
                float4 vv = *(const float4*)&Vs[jj][d];
                o[d + 0] = fmaf(p, vv.x, o[d + 0]);
                o[d + 1] = fmaf(p, vv.y, o[d + 1]);
                o[d + 2] = fmaf(p, vv.z, o[d + 2]);
                o[d + 3] = fmaf(p, vv.w, o[d + 3]);
            }
        }
    }

    const float inv = 1.0f / l;
    float* Op = O + ((size_t)b * S_ + r) * E_ + h * D_;
#pragma unroll
    for (int d = 0; d < D_; d++) Op[d] = o[d] * inv;
}

// ============================================================================
// Launch
// ============================================================================
extern "C" void kernel_launch(void* const* d_in, const int* in_sizes, int n_in,
                              void* d_out, int out_size) {
    (void)in_sizes; (void)n_in; (void)out_size;

    const float* q  = (const float*)d_in[0];
    const float* k  = (const float*)d_in[1];
    const float* v  = (const float*)d_in[2];
    const float* Wq = (const float*)d_in[4];
    const float* bq = (const float*)d_in[5];
    const float* Wk = (const float*)d_in[6];
    const float* bk = (const float*)d_in[7];
    const float* Wv = (const float*)d_in[8];
    const float* bv = (const float*)d_in[9];
    const float* Wo = (const float*)d_in[10];
    const float* bo = (const float*)d_in[11];
    float* out = (float*)d_out;

    float *pQ, *pK, *pV, *pC;
    cudaGetSymbolAddress((void**)&pQ, g_Q);
    cudaGetSymbolAddress((void**)&pK, g_K);
    cudaGetSymbolAddress((void**)&pV, g_V);
    cudaGetSymbolAddress((void**)&pC, g_C);

    cudaFuncSetAttribute(gemm_mma, cudaFuncAttributeMaxDynamicSharedMemorySize,
                         GM_DSMEM);

    const int M = B_ * S_;   // 4096
    const int N = E_;        // 1024
    const int K = E_;        // 1024

    dim3 ggrid(N / 128, M / 128);   // (8, 32)
    dim3 gblk(256);

    gemm_mma<<<ggrid, gblk, GM_DSMEM>>>(q, Wq, bq, pQ, M, N, K);
    gemm_mma<<<ggrid, gblk, GM_DSMEM>>>(k, Wk, bk, pK, M, N, K);
    gemm_mma<<<ggrid, gblk, GM_DSMEM>>>(v, Wv, bv, pV, M, N, K);

    dim3 agrid(S_ / AT_ROWS, H_, B_);   // (16, 16, 2)
    flash_attn_causal<<<agrid, AT_ROWS>>>(pQ, pK, pV, pC);

    gemm_mma<<<ggrid, gblk, GM_DSMEM>>>(pC, Wo, bo, out, M, N, K);
}

// round 5
// speedup vs baseline: 3.4365x; 2.5050x over previous
#include <cuda_runtime.h>
#include <cuda_bf16.h>
#include <math.h>

#define B_ 2
#define S_ 2048
#define E_ 1024
#define H_ 16
#define D_ 64

// Scratch (allocation-free rule: __device__ globals)
__device__ float g_Q[B_ * S_ * E_];
__device__ float g_K[B_ * S_ * E_];
__device__ float g_V[B_ * S_ * E_];
__device__ float g_C[B_ * S_ * E_];

// ============================================================================
// Helpers
// ============================================================================
__device__ __forceinline__ unsigned smem_u32(const void* p) {
    unsigned a;
    asm("{ .reg .u64 t; cvta.to.shared.u64 t, %1; cvt.u32.u64 %0, t; }"
        : "=r"(a) : "l"(p));
    return a;
}

#define STS128(r0, r1, r2, r3, sa) \
    asm volatile("st.shared.v4.b32 [%0], {%1, %2, %3, %4};" \
                 :: "r"(sa), "r"(r0), "r"(r1), "r"(r2), "r"(r3) : "memory")

#define CP16(dst, src) \
    asm volatile("cp.async.cg.shared.global [%0], [%1], 16;" \
                 :: "r"((unsigned)(dst)), "l"(src) : "memory")
#define CP_COMMIT() asm volatile("cp.async.commit_group;" ::: "memory")
#define CP_WAIT(n)  asm volatile("cp.async.wait_group %0;" :: "n"(n) : "memory")

__device__ __forceinline__ void ldsm4(unsigned* r, unsigned addr) {
    asm volatile("ldmatrix.sync.aligned.m8n8.x4.shared.b16 {%0,%1,%2,%3}, [%4];"
                 : "=r"(r[0]), "=r"(r[1]), "=r"(r[2]), "=r"(r[3]) : "r"(addr));
}
__device__ __forceinline__ void ldsm4t(unsigned* r, unsigned addr) {
    asm volatile("ldmatrix.sync.aligned.m8n8.x4.trans.shared.b16 {%0,%1,%2,%3}, [%4];"
                 : "=r"(r[0]), "=r"(r[1]), "=r"(r[2]), "=r"(r[3]) : "r"(addr));
}

__device__ __forceinline__ void mma16816(float* d, const unsigned* a,
                                         unsigned b0, unsigned b1) {
    asm volatile(
        "mma.sync.aligned.m16n8k16.row.col.f32.bf16.bf16.f32 "
        "{%0,%1,%2,%3}, {%4,%5,%6,%7}, {%8,%9}, {%0,%1,%2,%3};"
        : "+f"(d[0]), "+f"(d[1]), "+f"(d[2]), "+f"(d[3])
        : "r"(a[0]), "r"(a[1]), "r"(a[2]), "r"(a[3]), "r"(b0), "r"(b1));
}

__device__ __forceinline__ unsigned pack_bf2(float flo, float fhi) {
    unsigned r;
    asm("cvt.rn.bf16x2.f32 %0, %1, %2;" : "=r"(r) : "f"(fhi), "f"(flo));
    return r;
}
__device__ __forceinline__ void split2(float x0, float x1, unsigned& hi, unsigned& lo) {
    hi = pack_bf2(x0, x1);
    float h0 = __uint_as_float(hi << 16);
    float h1 = __uint_as_float(hi & 0xFFFF0000u);
    lo = pack_bf2(x0 - h0, x1 - h1);
}

// fast 2^t on the fma pipe (t <= 0), err ~2e-6
__device__ __forceinline__ float exp2p(float t) {
    t = fmaxf(t, -126.0f);
    float z = t + 12582912.0f;          // round-to-nearest int in mantissa
    float r = t - (z - 12582912.0f);
    float p = 0.0013333558f;
    p = fmaf(p, r, 0.0096181291f);
    p = fmaf(p, r, 0.0555041087f);
    p = fmaf(p, r, 0.2402265069f);
    p = fmaf(p, r, 0.6931471806f);
    p = fmaf(p, r, 1.0f);
    unsigned eb = (__float_as_uint(z) << 23) + 0x3F800000u;
    return __uint_as_float(eb) * p;
}

#define SW128(o) ((o) ^ (((o) >> 3) & 0x70))

// ============================================================================
// GEMM (NT): C[M,N] = A[M,K] @ W[N,K]^T + bias[N]  (unchanged from R3)
// ============================================================================
#define PIECE 8192
#define STG_BYTES (4 * PIECE)
#define GM_DSMEM (2 * STG_BYTES)

__global__ __launch_bounds__(256)
void gemm_mma(const float* __restrict__ A, const float* __restrict__ W,
              const float* __restrict__ bias, float* __restrict__ C,
              int M, int N, int K) {
    extern __shared__ char smem_raw[];
    const unsigned sbase = smem_u32(smem_raw);
    const int tid = threadIdx.x;
    const int lane = tid & 31;
    const int wid = tid >> 5;
    const int bm = blockIdx.y * 128;
    const int bn = blockIdx.x * 128;

    const int srow = tid >> 1;
    const int sseg = tid & 1;
    const float* Ap = A + (size_t)(bm + srow) * K + sseg * 16;
    const float* Wp = W + (size_t)(bn + srow) * K + sseg * 16;
    const unsigned sg = (srow >> 1) & 3;
    const unsigned st0 = (unsigned)(srow * 64) + ((((unsigned)sseg * 2 + 0) ^ sg) << 4);
    const unsigned st1 = (unsigned)(srow * 64) + ((((unsigned)sseg * 2 + 1) ^ sg) << 4);

    float4 ra0, ra1, ra2, ra3, rw0, rw1, rw2, rw3;

    auto loadc = [&](int c) {
        const float* pa = Ap + c * 32;
        ra0 = *(const float4*)(pa);
        ra1 = *(const float4*)(pa + 4);
        ra2 = *(const float4*)(pa + 8);
        ra3 = *(const float4*)(pa + 12);
        const float* pw = Wp + c * 32;
        rw0 = *(const float4*)(pw);
        rw1 = *(const float4*)(pw + 4);
        rw2 = *(const float4*)(pw + 8);
        rw3 = *(const float4*)(pw + 12);
    };

    auto storec = [&](unsigned stg) {
        unsigned h[8], l[8];
        split2(ra0.x, ra0.y, h[0], l[0]); split2(ra0.z, ra0.w, h[1], l[1]);
        split2(ra1.x, ra1.y, h[2], l[2]); split2(ra1.z, ra1.w, h[3], l[3]);
        split2(ra2.x, ra2.y, h[4], l[4]); split2(ra2.z, ra2.w, h[5], l[5]);
        split2(ra3.x, ra3.y, h[6], l[6]); split2(ra3.z, ra3.w, h[7], l[7]);
        STS128(h[0], h[1], h[2], h[3], stg + st0);
        STS128(h[4], h[5], h[6], h[7], stg + st1);
        STS128(l[0], l[1], l[2], l[3], stg + PIECE + st0);
        STS128(l[4], l[5], l[6], l[7], stg + PIECE + st1);
        split2(rw0.x, rw0.y, h[0], l[0]); split2(rw0.z, rw0.w, h[1], l[1]);
        split2(rw1.x, rw1.y, h[2], l[2]); split2(rw1.z, rw1.w, h[3], l[3]);
        split2(rw2.x, rw2.y, h[4], l[4]); split2(rw2.z, rw2.w, h[5], l[5]);
        split2(rw3.x, rw3.y, h[6], l[6]); split2(rw3.z, rw3.w, h[7], l[7]);
        STS128(h[0], h[1], h[2], h[3], stg + 2 * PIECE + st0);
        STS128(h[4], h[5], h[6], h[7], stg + 2 * PIECE + st1);
        STS128(l[0], l[1], l[2], l[3], stg + 3 * PIECE + st0);
        STS128(l[4], l[5], l[6], l[7], stg + 3 * PIECE + st1);
    };

    const int wm = (wid & 3) * 32;
    const int wn = (wid >> 2) * 64;
    const unsigned aRow = (unsigned)((wm + (lane & 15)) * 64);
    const unsigned aG = (((unsigned)lane & 15) >> 1) & 3;
    const unsigned aHalf = (unsigned)lane >> 4;
    const unsigned bLocal = ((unsigned)lane & 7) + (((unsigned)lane & 16) >> 1);
    const unsigned bRow = (unsigned)((wn + (int)bLocal) * 64);
    const unsigned bG = (bLocal >> 1) & 3;
    const unsigned bHalf = ((unsigned)lane >> 3) & 1;

    float acc[2][8][4];
#pragma unroll
    for (int i = 0; i < 2; i++)
#pragma unroll
        for (int j = 0; j < 8; j++)
#pragma unroll
            for (int t = 0; t < 4; t++) acc[i][j][t] = 0.0f;

    auto compute = [&](unsigned stg) {
#pragma unroll
        for (int ks = 0; ks < 2; ks++) {
            unsigned ah0[4], ah1[4], al0[4], al1[4];
            const unsigned aoffs = (((unsigned)(2 * ks) + aHalf) ^ aG) << 4;
            ldsm4(ah0, stg + aRow + aoffs);
            ldsm4(ah1, stg + aRow + 1024 + aoffs);
            ldsm4(al0, stg + PIECE + aRow + aoffs);
            ldsm4(al1, stg + PIECE + aRow + 1024 + aoffs);
            const unsigned boffs = (((unsigned)(2 * ks) + bHalf) ^ bG) << 4;
#pragma unroll
            for (int ng = 0; ng < 4; ng++) {
                unsigned bh[4], bl[4];
                ldsm4(bh, stg + 2 * PIECE + bRow + ng * 1024 + boffs);
                ldsm4(bl, stg + 3 * PIECE + bRow + ng * 1024 + boffs);
                mma16816(acc[0][2 * ng],     ah0, bh[0], bh[1]);
                mma16816(acc[0][2 * ng + 1], ah0, bh[2], bh[3]);
                mma16816(acc[1][2 * ng],     ah1, bh[0], bh[1]);
                mma16816(acc[1][2 * ng + 1], ah1, bh[2], bh[3]);
                mma16816(acc[0][2 * ng],     ah0, bl[0], bl[1]);
                mma16816(acc[0][2 * ng + 1], ah0, bl[2], bl[3]);
                mma16816(acc[1][2 * ng],     ah1, bl[0], bl[1]);
                mma16816(acc[1][2 * ng + 1], ah1, bl[2], bl[3]);
                mma16816(acc[0][2 * ng],     al0, bh[0], bh[1]);
                mma16816(acc[0][2 * ng + 1], al0, bh[2], bh[3]);
                mma16816(acc[1][2 * ng],     al1, bh[0], bh[1]);
                mma16816(acc[1][2 * ng + 1], al1, bh[2], bh[3]);
            }
        }
    };

    const int nchunk = K / 32;
    loadc(0);
    storec(sbase);
    __syncthreads();
    for (int c = 0; c < nchunk; c++) {
        const unsigned stg = sbase + (unsigned)(c & 1) * STG_BYTES;
        if (c + 1 < nchunk) loadc(c + 1);
        compute(stg);
        if (c + 1 < nchunk) storec(sbase + (unsigned)((c + 1) & 1) * STG_BYTES);
        __syncthreads();
    }

    const int r0 = bm + wm + (lane >> 2);
    const int c0 = bn + wn + (lane & 3) * 2;
#pragma unroll
    for (int mf = 0; mf < 2; mf++) {
#pragma unroll
        for (int ng = 0; ng < 8; ng++) {
            const int row = r0 + mf * 16;
            const int col = c0 + ng * 8;
            const float2 bb = *(const float2*)(bias + col);
            float2 v0, v1;
            v0.x = acc[mf][ng][0] + bb.x;
            v0.y = acc[mf][ng][1] + bb.y;
            v1.x = acc[mf][ng][2] + bb.x;
            v1.y = acc[mf][ng][3] + bb.y;
            *(float2*)(C + (size_t)row * N + col) = v0;
            *(float2*)(C + (size_t)(row + 8) * N + col) = v1;
        }
    }
}

// ============================================================================
// Flash attention v2 on mma.sync (bf16 3-term split, causal, base-2 softmax).
// CTA: 128 q-rows, key tiles of 64. 8 warps x (16q x 64keys / 64d).
// smem: [0,32K) bf16 bufs (Khi|Klo|Vhi|Vlo, 8K each; overlaid w/ Q staging)
//       [32K,96K) fp32 K/V double-buffered cp.async stages.
// grid = (S/128, H, B), block = 256.
// ============================================================================
#define FA_DSMEM 98304
#define SM_KHI 0
#define SM_KLO 8192
#define SM_VHI 16384
#define SM_VLO 24576
#define SM_ST  32768
#define QSC 0.1803368801111244f   // 0.125 * log2(e)

__global__ __launch_bounds__(256, 1)
void flash_attn_mma(const float* __restrict__ Q, const float* __restrict__ K,
                    const float* __restrict__ V, float* __restrict__ O) {
    extern __shared__ char sm[];
    const unsigned sb = smem_u32(sm);
    const int tid = threadIdx.x;
    const int lane = tid & 31;
    const int wid = tid >> 5;
    const int b = blockIdx.z;
    const int h = blockIdx.y;
    const int bx = blockIdx.x;
    const int bq = bx * 128;
    const int wm = wid * 16;

    // ---- stage Q (fp32 -> scaled bf16 hi/lo, swizzled) ----
#pragma unroll
    for (int i = 0; i < 4; i++) {
        const int g = tid + i * 256;
        const int row = g >> 3, seg = g & 7;
        const float* p = Q + ((size_t)(b * S_ + bq + row)) * E_ + h * 64 + seg * 8;
        float4 x0 = *(const float4*)p;
        float4 x1 = *(const float4*)(p + 4);
        x0.x *= QSC; x0.y *= QSC; x0.z *= QSC; x0.w *= QSC;
        x1.x *= QSC; x1.y *= QSC; x1.z *= QSC; x1.w *= QSC;
        unsigned h0, h1, h2, h3, l0, l1, l2, l3;
        split2(x0.x, x0.y, h0, l0); split2(x0.z, x0.w, h1, l1);
        split2(x1.x, x1.y, h2, l2); split2(x1.z, x1.w, h3, l3);
        const unsigned sw = SW128((unsigned)(row * 128 + seg * 16));
        STS128(h0, h1, h2, h3, sb + sw);            // qhi overlays [0,16K)
        STS128(l0, l1, l2, l3, sb + 16384 + sw);    // qlo overlays [16K,32K)
    }

    const int ntiles = 2 * bx + 2;

    // ---- prefetch fp32 K/V tile 0 ----
    {
        const unsigned stb = sb + SM_ST;
#pragma unroll
        for (int i = 0; i < 4; i++) {
            const int idx = tid + i * 256;
            const int row = idx >> 4, seg = idx & 15;
            const size_t src = ((size_t)(b * S_ + row)) * E_ + h * 64 + seg * 4;
            CP16(stb + row * 256 + seg * 16, K + src);
            CP16(stb + 16384 + row * 256 + seg * 16, V + src);
        }
        CP_COMMIT();
    }
    __syncthreads();   // Q smem ready

    // ---- load Q fragments into registers ----
    unsigned aQh[4][4], aQl[4][4];
    {
        const unsigned qrow = (unsigned)((wm + (lane & 15)) * 128);
        const unsigned qhalf = ((unsigned)lane >> 4) * 16;
#pragma unroll
        for (int kc = 0; kc < 4; kc++) {
            const unsigned sw = SW128(qrow + (unsigned)(kc * 32) + qhalf);
            ldsm4(aQh[kc], sb + sw);
            ldsm4(aQl[kc], sb + 16384 + sw);
        }
    }

    float accO[8][4];
#pragma unroll
    for (int f = 0; f < 8; f++)
#pragma unroll
        for (int j = 0; j < 4; j++) accO[f][j] = 0.0f;
    float m0 = -1e30f, m1 = -1e30f, l0 = 0.0f, l1 = 0.0f;

    const unsigned bLoc = ((unsigned)lane & 7) + (((unsigned)lane & 16) >> 1);
    const unsigned bHalf = (((unsigned)lane >> 3) & 1) * 16;
    const unsigned vRowBase = ((unsigned)lane & 7) + ((unsigned)lane & 8);
    const unsigned vHalf = (((unsigned)lane >> 4) & 1) * 16;

    for (int t = 0; t < ntiles; t++) {
        // prefetch t+1
        if (t + 1 < ntiles) {
            const int j1 = (t + 1) * 64;
            const unsigned stb = sb + SM_ST + (unsigned)((t + 1) & 1) * 32768;
#pragma unroll
            for (int i = 0; i < 4; i++) {
                const int idx = tid + i * 256;
                const int row = idx >> 4, seg = idx & 15;
                const size_t src = ((size_t)(b * S_ + j1 + row)) * E_ + h * 64 + seg * 4;
                CP16(stb + row * 256 + seg * 16, K + src);
                CP16(stb + 16384 + row * 256 + seg * 16, V + src);
            }
            CP_COMMIT();
            CP_WAIT(1);
        } else {
            CP_WAIT(0);
        }
        __syncthreads();   // stage t visible; prev-tile mma done (bf16 bufs free)

        // ---- convert fp32 stage -> bf16 hi/lo (K and V) ----
        {
            const char* stg = sm + SM_ST + (size_t)(t & 1) * 32768;
            const float* stK = (const float*)stg;
            const float* stV = (const float*)(stg + 16384);
#pragma unroll
            for (int i = 0; i < 2; i++) {
                const int g = tid + i * 256;
                const int row = g >> 3, seg = g & 7;
                const unsigned sw = SW128((unsigned)(row * 128 + seg * 16));
                float4 x0 = *(const float4*)(stK + row * 64 + seg * 8);
                float4 x1 = *(const float4*)(stK + row * 64 + seg * 8 + 4);
                unsigned h0, h1, h2, h3, q0, q1, q2, q3;
                split2(x0.x, x0.y, h0, q0); split2(x0.z, x0.w, h1, q1);
                split2(x1.x, x1.y, h2, q2); split2(x1.z, x1.w, h3, q3);
                STS128(h0, h1, h2, h3, sb + SM_KHI + sw);
                STS128(q0, q1, q2, q3, sb + SM_KLO + sw);
                x0 = *(const float4*)(stV + row * 64 + seg * 8);
                x1 = *(const float4*)(stV + row * 64 + seg * 8 + 4);
                split2(x0.x, x0.y, h0, q0); split2(x0.z, x0.w, h1, q1);
                split2(x1.x, x1.y, h2, q2); split2(x1.z, x1.w, h3, q3);
                STS128(h0, h1, h2, h3, sb + SM_VHI + sw);
                STS128(q0, q1, q2, q3, sb + SM_VLO + sw);
            }
        }
        __syncthreads();

        const int j0 = t * 64;

        // ---- S = Q K^T (3-term split) ----
        float accS[8][4];
#pragma unroll
        for (int f = 0; f < 8; f++)
#pragma unroll
            for (int j = 0; j < 4; j++) accS[f][j] = 0.0f;

#pragma unroll
        for (int kc = 0; kc < 4; kc++) {
#pragma unroll
            for (int ng = 0; ng < 4; ng++) {
                const unsigned row = (unsigned)(ng * 16) + bLoc;
                const unsigned sw = SW128(row * 128 + (unsigned)(kc * 32) + bHalf);
                unsigned kh[4], kl[4];
                ldsm4(kh, sb + SM_KHI + sw);
                ldsm4(kl, sb + SM_KLO + sw);
                mma16816(accS[2 * ng],     aQh[kc], kh[0], kh[1]);
                mma16816(accS[2 * ng + 1], aQh[kc], kh[2], kh[3]);
                mma16816(accS[2 * ng],     aQl[kc], kh[0], kh[1]);
                mma16816(accS[2 * ng + 1], aQl[kc], kh[2], kh[3]);
                mma16816(accS[2 * ng],     aQh[kc], kl[0], kl[1]);
                mma16816(accS[2 * ng + 1], aQh[kc], kl[2], kl[3]);
            }
        }

        const int row0 = bq + wm + (lane >> 2);
        const int row1 = row0 + 8;

        // ---- causal mask (only tiles that can mask this warp's rows) ----
        if (j0 + 63 > bq + wm) {
#pragma unroll
            for (int f = 0; f < 8; f++) {
                const int c0 = j0 + f * 8 + (lane & 3) * 2;
                if (c0 > row0)     accS[f][0] = -1e30f;
                if (c0 + 1 > row0) accS[f][1] = -1e30f;
                if (c0 > row1)     accS[f][2] = -1e30f;
                if (c0 + 1 > row1) accS[f][3] = -1e30f;
            }
        }

        // ---- online softmax: row max, rescale ----
        float rm0 = -1e30f, rm1 = -1e30f;
#pragma unroll
        for (int f = 0; f < 8; f++) {
            rm0 = fmaxf(rm0, fmaxf(accS[f][0], accS[f][1]));
            rm1 = fmaxf(rm1, fmaxf(accS[f][2], accS[f][3]));
        }
        rm0 = fmaxf(rm0, __shfl_xor_sync(0xFFFFFFFF, rm0, 1));
        rm0 = fmaxf(rm0, __shfl_xor_sync(0xFFFFFFFF, rm0, 2));
        rm1 = fmaxf(rm1, __shfl_xor_sync(0xFFFFFFFF, rm1, 1));
        rm1 = fmaxf(rm1, __shfl_xor_sync(0xFFFFFFFF, rm1, 2));
        const float mn0 = fmaxf(m0, rm0);
        const float mn1 = fmaxf(m1, rm1);
        const float sc0 = exp2p(m0 - mn0);
        const float sc1 = exp2p(m1 - mn1);
        m0 = mn0; m1 = mn1;
        l0 *= sc0; l1 *= sc1;
#pragma unroll
        for (int f = 0; f < 8; f++) {
            accO[f][0] *= sc0; accO[f][1] *= sc0;
            accO[f][2] *= sc1; accO[f][3] *= sc1;
        }

        // ---- P = exp2(S - m); O += P V (3-term split) ----
        float sump0 = 0.0f, sump1 = 0.0f;
#pragma unroll
        for (int kc = 0; kc < 4; kc++) {
            const int f0 = 2 * kc, f1 = 2 * kc + 1;
            const float p00 = exp2p(accS[f0][0] - m0);
            const float p01 = exp2p(accS[f0][1] - m0);
            const float p02 = exp2p(accS[f0][2] - m1);
            const float p03 = exp2p(accS[f0][3] - m1);
            const float p10 = exp2p(accS[f1][0] - m0);
            const float p11 = exp2p(accS[f1][1] - m0);
            const float p12 = exp2p(accS[f1][2] - m1);
            const float p13 = exp2p(accS[f1][3] - m1);
            sump0 += (p00 + p01) + (p10 + p11);
            sump1 += (p02 + p03) + (p12 + p13);
            unsigned ph[4], pl[4];
            split2(p00, p01, ph[0], pl[0]);
            split2(p02, p03, ph[1], pl[1]);
            split2(p10, p11, ph[2], pl[2]);
            split2(p12, p13, ph[3], pl[3]);

            const unsigned vrow = (unsigned)(kc * 16) + vRowBase;
#pragma unroll
            for (int nd = 0; nd < 4; nd++) {
                const unsigned sw = SW128(vrow * 128 + (unsigned)(nd * 32) + vHalf);
                unsigned vh[4], vl[4];
                ldsm4t(vh, sb + SM_VHI + sw);
                ldsm4t(vl, sb + SM_VLO + sw);
                mma16816(accO[2 * nd],     ph, vh[0], vh[1]);
                mma16816(accO[2 * nd + 1], ph, vh[2], vh[3]);
                mma16816(accO[2 * nd],     pl, vh[0], vh[1]);
                mma16816(accO[2 * nd + 1], pl, vh[2], vh[3]);
                mma16816(accO[2 * nd],     ph, vl[0], vl[1]);
                mma16816(accO[2 * nd + 1], ph, vl[2], vl[3]);
            }
        }
        l0 += sump0;
        l1 += sump1;
    }

    // ---- finalize: reduce l across quad, write O ----
    l0 += __shfl_xor_sync(0xFFFFFFFF, l0, 1);
    l0 += __shfl_xor_sync(0xFFFFFFFF, l0, 2);
    l1 += __shfl_xor_sync(0xFFFFFFFF, l1, 1);
    l1 += __shfl_xor_sync(0xFFFFFFFF, l1, 2);
    const float inv0 = 1.0f / l0;
    const float inv1 = 1.0f / l1;

    const int row0 = bq + wm + (lane >> 2);
    float* O0 = O + ((size_t)(b * S_ + row0)) * E_ + h * 64;
    float* O1 = O + ((size_t)(b * S_ + row0 + 8)) * E_ + h * 64;
#pragma unroll
    for (int f = 0; f < 8; f++) {
        const int col = f * 8 + (lane & 3) * 2;
        float2 v0, v1;
        v0.x = accO[f][0] * inv0; v0.y = accO[f][1] * inv0;
        v1.x = accO[f][2] * inv1; v1.y = accO[f][3] * inv1;
        *(float2*)(O0 + col) = v0;
        *(float2*)(O1 + col) = v1;
    }
}

// ============================================================================
// Launch
// ============================================================================
extern "C" void kernel_launch(void* const* d_in, const int* in_sizes, int n_in,
                              void* d_out, int out_size) {
    (void)in_sizes; (void)n_in; (void)out_size;

    const float* q  = (const float*)d_in[0];
    const float* k  = (const float*)d_in[1];
    const float* v  = (const float*)d_in[2];
    const float* Wq = (const float*)d_in[4];
    const float* bq = (const float*)d_in[5];
    const float* Wk = (const float*)d_in[6];
    const float* bk = (const float*)d_in[7];
    const float* Wv = (const float*)d_in[8];
    const float* bv = (const float*)d_in[9];
    const float* Wo = (const float*)d_in[10];
    const float* bo = (const float*)d_in[11];
    float* out = (float*)d_out;

    float *pQ, *pK, *pV, *pC;
    cudaGetSymbolAddress((void**)&pQ, g_Q);
    cudaGetSymbolAddress((void**)&pK, g_K);
    cudaGetSymbolAddress((void**)&pV, g_V);
    cudaGetSymbolAddress((void**)&pC, g_C);

    cudaFuncSetAttribute(gemm_mma, cudaFuncAttributeMaxDynamicSharedMemorySize,
                         GM_DSMEM);
    cudaFuncSetAttribute(flash_attn_mma, cudaFuncAttributeMaxDynamicSharedMemorySize,
                         FA_DSMEM);

    const int M = B_ * S_;   // 4096
    const int N = E_;        // 1024
    const int K = E_;        // 1024

    dim3 ggrid(N / 128, M / 128);   // (8, 32)
    dim3 gblk(256);

    gemm_mma<<<ggrid, gblk, GM_DSMEM>>>(q, Wq, bq, pQ, M, N, K);
    gemm_mma<<<ggrid, gblk, GM_DSMEM>>>(k, Wk, bk, pK, M, N, K);
    gemm_mma<<<ggrid, gblk, GM_DSMEM>>>(v, Wv, bv, pV, M, N, K);

    dim3 agrid(S_ / 128, H_, B_);   // (16, 16, 2)
    flash_attn_mma<<<agrid, 256, FA_DSMEM>>>(pQ, pK, pV, pC);

    gemm_mma<<<ggrid, gblk, GM_DSMEM>>>(pC, Wo, bo, out, M, N, K);
}

// round 6
// speedup vs baseline: 3.9412x; 1.1469x over previous
#include <cuda_runtime.h>
#include <cuda_bf16.h>
#include <math.h>

#define B_ 2
#define S_ 2048
#define E_ 1024
#define H_ 16
#define D_ 64

// Scratch (allocation-free rule: __device__ globals)
__device__ unsigned short g_Qh[B_ * S_ * E_];
__device__ unsigned short g_Ql[B_ * S_ * E_];
__device__ unsigned short g_Kh[B_ * S_ * E_];
__device__ unsigned short g_Kl[B_ * S_ * E_];
__device__ unsigned short g_Vh[B_ * S_ * E_];
__device__ unsigned short g_Vl[B_ * S_ * E_];
__device__ float g_C[B_ * S_ * E_];

// ============================================================================
// Helpers
// ============================================================================
__device__ __forceinline__ unsigned smem_u32(const void* p) {
    unsigned a;
    asm("{ .reg .u64 t; cvta.to.shared.u64 t, %1; cvt.u32.u64 %0, t; }"
        : "=r"(a) : "l"(p));
    return a;
}

#define STS128(r0, r1, r2, r3, sa) \
    asm volatile("st.shared.v4.b32 [%0], {%1, %2, %3, %4};" \
                 :: "r"(sa), "r"(r0), "r"(r1), "r"(r2), "r"(r3) : "memory")

#define CP16(dst, src) \
    asm volatile("cp.async.cg.shared.global [%0], [%1], 16;" \
                 :: "r"((unsigned)(dst)), "l"(src) : "memory")
#define CP_COMMIT() asm volatile("cp.async.commit_group;" ::: "memory")
#define CP_WAIT(n)  asm volatile("cp.async.wait_group %0;" :: "n"(n) : "memory")

__device__ __forceinline__ void ldsm4(unsigned* r, unsigned addr) {
    asm volatile("ldmatrix.sync.aligned.m8n8.x4.shared.b16 {%0,%1,%2,%3}, [%4];"
                 : "=r"(r[0]), "=r"(r[1]), "=r"(r[2]), "=r"(r[3]) : "r"(addr));
}
__device__ __forceinline__ void ldsm4t(unsigned* r, unsigned addr) {
    asm volatile("ldmatrix.sync.aligned.m8n8.x4.trans.shared.b16 {%0,%1,%2,%3}, [%4];"
                 : "=r"(r[0]), "=r"(r[1]), "=r"(r[2]), "=r"(r[3]) : "r"(addr));
}

__device__ __forceinline__ void mma16816(float* d, const unsigned* a,
                                         unsigned b0, unsigned b1) {
    asm volatile(
        "mma.sync.aligned.m16n8k16.row.col.f32.bf16.bf16.f32 "
        "{%0,%1,%2,%3}, {%4,%5,%6,%7}, {%8,%9}, {%0,%1,%2,%3};"
        : "+f"(d[0]), "+f"(d[1]), "+f"(d[2]), "+f"(d[3])
        : "r"(a[0]), "r"(a[1]), "r"(a[2]), "r"(a[3]), "r"(b0), "r"(b1));
}

__device__ __forceinline__ unsigned pack_bf2(float flo, float fhi) {
    unsigned r;
    asm("cvt.rn.bf16x2.f32 %0, %1, %2;" : "=r"(r) : "f"(fhi), "f"(flo));
    return r;
}
__device__ __forceinline__ void split2(float x0, float x1, unsigned& hi, unsigned& lo) {
    hi = pack_bf2(x0, x1);
    float h0 = __uint_as_float(hi << 16);
    float h1 = __uint_as_float(hi & 0xFFFF0000u);
    lo = pack_bf2(x0 - h0, x1 - h1);
}

// fast 2^t on the fma pipe (t <= 0), err ~2e-6
__device__ __forceinline__ float exp2p(float t) {
    t = fmaxf(t, -126.0f);
    float z = t + 12582912.0f;
    float r = t - (z - 12582912.0f);
    float p = 0.0013333558f;
    p = fmaf(p, r, 0.0096181291f);
    p = fmaf(p, r, 0.0555041087f);
    p = fmaf(p, r, 0.2402265069f);
    p = fmaf(p, r, 0.6931471806f);
    p = fmaf(p, r, 1.0f);
    unsigned eb = (__float_as_uint(z) << 23) + 0x3F800000u;
    return __uint_as_float(eb) * p;
}

#define SW128(o) ((o) ^ (((o) >> 3) & 0x70))
#define QSC 0.1803368801111244f   // 0.125 * log2(e)

// ============================================================================
// GEMM (NT): Y[M,N] = A[M,K] @ W[N,K]^T + bias[N], then either
//   fp32 C store (Hout==nullptr) or scaled bf16 hi/lo split store.
// ============================================================================
#define PIECE 8192
#define STG_BYTES (4 * PIECE)
#define GM_DSMEM (2 * STG_BYTES)

__global__ __launch_bounds__(256)
void gemm_mma(const float* __restrict__ A, const float* __restrict__ W,
              const float* __restrict__ bias, float* __restrict__ C,
              unsigned* __restrict__ Hout, unsigned* __restrict__ Lout,
              float oscale, int M, int N, int K) {
    extern __shared__ char smem_raw[];
    const unsigned sbase = smem_u32(smem_raw);
    const int tid = threadIdx.x;
    const int lane = tid & 31;
    const int wid = tid >> 5;
    const int bm = blockIdx.y * 128;
    const int bn = blockIdx.x * 128;

    const int srow = tid >> 1;
    const int sseg = tid & 1;
    const float* Ap = A + (size_t)(bm + srow) * K + sseg * 16;
    const float* Wp = W + (size_t)(bn + srow) * K + sseg * 16;
    const unsigned sg = (srow >> 1) & 3;
    const unsigned st0 = (unsigned)(srow * 64) + ((((unsigned)sseg * 2 + 0) ^ sg) << 4);
    const unsigned st1 = (unsigned)(srow * 64) + ((((unsigned)sseg * 2 + 1) ^ sg) << 4);

    float4 ra0, ra1, ra2, ra3, rw0, rw1, rw2, rw3;

    auto loadc = [&](int c) {
        const float* pa = Ap + c * 32;
        ra0 = *(const float4*)(pa);
        ra1 = *(const float4*)(pa + 4);
        ra2 = *(const float4*)(pa + 8);
        ra3 = *(const float4*)(pa + 12);
        const float* pw = Wp + c * 32;
        rw0 = *(const float4*)(pw);
        rw1 = *(const float4*)(pw + 4);
        rw2 = *(const float4*)(pw + 8);
        rw3 = *(const float4*)(pw + 12);
    };

    auto storec = [&](unsigned stg) {
        unsigned h[8], l[8];
        split2(ra0.x, ra0.y, h[0], l[0]); split2(ra0.z, ra0.w, h[1], l[1]);
        split2(ra1.x, ra1.y, h[2], l[2]); split2(ra1.z, ra1.w, h[3], l[3]);
        split2(ra2.x, ra2.y, h[4], l[4]); split2(ra2.z, ra2.w, h[5], l[5]);
        split2(ra3.x, ra3.y, h[6], l[6]); split2(ra3.z, ra3.w, h[7], l[7]);
        STS128(h[0], h[1], h[2], h[3], stg + st0);
        STS128(h[4], h[5], h[6], h[7], stg + st1);
        STS128(l[0], l[1], l[2], l[3], stg + PIECE + st0);
        STS128(l[4], l[5], l[6], l[7], stg + PIECE + st1);
        split2(rw0.x, rw0.y, h[0], l[0]); split2(rw0.z, rw0.w, h[1], l[1]);
        split2(rw1.x, rw1.y, h[2], l[2]); split2(rw1.z, rw1.w, h[3], l[3]);
        split2(rw2.x, rw2.y, h[4], l[4]); split2(rw2.z, rw2.w, h[5], l[5]);
        split2(rw3.x, rw3.y, h[6], l[6]); split2(rw3.z, rw3.w, h[7], l[7]);
        STS128(h[0], h[1], h[2], h[3], stg + 2 * PIECE + st0);
        STS128(h[4], h[5], h[6], h[7], stg + 2 * PIECE + st1);
        STS128(l[0], l[1], l[2], l[3], stg + 3 * PIECE + st0);
        STS128(l[4], l[5], l[6], l[7], stg + 3 * PIECE + st1);
    };

    const int wm = (wid & 3) * 32;
    const int wn = (wid >> 2) * 64;
    const unsigned aRow = (unsigned)((wm + (lane & 15)) * 64);
    const unsigned aG = (((unsigned)lane & 15) >> 1) & 3;
    const unsigned aHalf = (unsigned)lane >> 4;
    const unsigned bLocal = ((unsigned)lane & 7) + (((unsigned)lane & 16) >> 1);
    const unsigned bRow = (unsigned)((wn + (int)bLocal) * 64);
    const unsigned bG = (bLocal >> 1) & 3;
    const unsigned bHalf = ((unsigned)lane >> 3) & 1;

    float acc[2][8][4];
#pragma unroll
    for (int i = 0; i < 2; i++)
#pragma unroll
        for (int j = 0; j < 8; j++)
#pragma unroll
            for (int t = 0; t < 4; t++) acc[i][j][t] = 0.0f;

    auto compute = [&](unsigned stg) {
#pragma unroll
        for (int ks = 0; ks < 2; ks++) {
            unsigned ah0[4], ah1[4], al0[4], al1[4];
            const unsigned aoffs = (((unsigned)(2 * ks) + aHalf) ^ aG) << 4;
            ldsm4(ah0, stg + aRow + aoffs);
            ldsm4(ah1, stg + aRow + 1024 + aoffs);
            ldsm4(al0, stg + PIECE + aRow + aoffs);
            ldsm4(al1, stg + PIECE + aRow + 1024 + aoffs);
            const unsigned boffs = (((unsigned)(2 * ks) + bHalf) ^ bG) << 4;
#pragma unroll
            for (int ng = 0; ng < 4; ng++) {
                unsigned bh[4], bl[4];
                ldsm4(bh, stg + 2 * PIECE + bRow + ng * 1024 + boffs);
                ldsm4(bl, stg + 3 * PIECE + bRow + ng * 1024 + boffs);
                mma16816(acc[0][2 * ng],     ah0, bh[0], bh[1]);
                mma16816(acc[0][2 * ng + 1], ah0, bh[2], bh[3]);
                mma16816(acc[1][2 * ng],     ah1, bh[0], bh[1]);
                mma16816(acc[1][2 * ng + 1], ah1, bh[2], bh[3]);
                mma16816(acc[0][2 * ng],     ah0, bl[0], bl[1]);
                mma16816(acc[0][2 * ng + 1], ah0, bl[2], bl[3]);
                mma16816(acc[1][2 * ng],     ah1, bl[0], bl[1]);
                mma16816(acc[1][2 * ng + 1], ah1, bl[2], bl[3]);
                mma16816(acc[0][2 * ng],     al0, bh[0], bh[1]);
                mma16816(acc[0][2 * ng + 1], al0, bh[2], bh[3]);
                mma16816(acc[1][2 * ng],     al1, bh[0], bh[1]);
                mma16816(acc[1][2 * ng + 1], al1, bh[2], bh[3]);
            }
        }
    };

    const int nchunk = K / 32;
    loadc(0);
    storec(sbase);
    __syncthreads();
    for (int c = 0; c < nchunk; c++) {
        const unsigned stg = sbase + (unsigned)(c & 1) * STG_BYTES;
        if (c + 1 < nchunk) loadc(c + 1);
        compute(stg);
        if (c + 1 < nchunk) storec(sbase + (unsigned)((c + 1) & 1) * STG_BYTES);
        __syncthreads();
    }

    // ---- epilogue ----
    const int r0 = bm + wm + (lane >> 2);
    const int c0 = bn + wn + (lane & 3) * 2;
    if (Hout) {
#pragma unroll
        for (int mf = 0; mf < 2; mf++) {
#pragma unroll
            for (int ng = 0; ng < 8; ng++) {
                const int row = r0 + mf * 16;
                const int col = c0 + ng * 8;
                const float2 bb = *(const float2*)(bias + col);
                unsigned h0, l0, h1, l1;
                split2((acc[mf][ng][0] + bb.x) * oscale,
                       (acc[mf][ng][1] + bb.y) * oscale, h0, l0);
                split2((acc[mf][ng][2] + bb.x) * oscale,
                       (acc[mf][ng][3] + bb.y) * oscale, h1, l1);
                const size_t i0 = (size_t)row * (N / 2) + col / 2;
                const size_t i1 = (size_t)(row + 8) * (N / 2) + col / 2;
                Hout[i0] = h0; Lout[i0] = l0;
                Hout[i1] = h1; Lout[i1] = l1;
            }
        }
    } else {
#pragma unroll
        for (int mf = 0; mf < 2; mf++) {
#pragma unroll
            for (int ng = 0; ng < 8; ng++) {
                const int row = r0 + mf * 16;
                const int col = c0 + ng * 8;
                const float2 bb = *(const float2*)(bias + col);
                float2 v0, v1;
                v0.x = acc[mf][ng][0] + bb.x;
                v0.y = acc[mf][ng][1] + bb.y;
                v1.x = acc[mf][ng][2] + bb.x;
                v1.y = acc[mf][ng][3] + bb.y;
                *(float2*)(C + (size_t)row * N + col) = v0;
                *(float2*)(C + (size_t)(row + 8) * N + col) = v1;
            }
        }
    }
}

// ============================================================================
// Flash attention on pre-split bf16 inputs (causal, base-2 softmax).
// CTA: 128 q-rows x 64-key tiles; 8 warps x 16q. 3-stage cp.async KV ring,
// ONE syncthreads per tile. LPT grid order (heavy bx first).
// smem: [0,96K) KV ring (3 x [Khi|Klo|Vhi|Vlo] x 8K), [96K,128K) Qhi|Qlo.
// ============================================================================
#define FA_DSMEM 131072
#define KV_STG 32768
#define SM_Q 98304

__global__ __launch_bounds__(256, 1)
void flash_attn_bf16(const unsigned short* __restrict__ Qh,
                     const unsigned short* __restrict__ Ql,
                     const unsigned short* __restrict__ Kh,
                     const unsigned short* __restrict__ Kl,
                     const unsigned short* __restrict__ Vh,
                     const unsigned short* __restrict__ Vl,
                     float* __restrict__ O) {
    extern __shared__ char sm[];
    const unsigned sb = smem_u32(sm);
    const int tid = threadIdx.x;
    const int lane = tid & 31;
    const int wid = tid >> 5;

    // LPT remap: heavy (large bx) CTAs first
    const int idx = blockIdx.x;
    const int bx = 15 - (idx >> 5);
    const int rem = idx & 31;
    const int h = rem & 15;
    const int b = rem >> 4;
    const int bq = bx * 128;
    const int wm = wid * 16;
    const int ntiles = 2 * bx + 2;

    // KV tile stage: 64 rows x 64 bf16 per buf, swizzled; 8 cp.16/thread
    auto stage_kv = [&](int t) {
        const unsigned stb = sb + (unsigned)(t % 3) * KV_STG;
        const int j0 = t * 64;
        const size_t rb = ((size_t)(b * S_ + j0)) * E_ + h * 64;
#pragma unroll
        for (int i = 0; i < 2; i++) {
            const int g = tid + i * 256;
            const int row = g >> 3, seg = g & 7;
            const unsigned sw = SW128((unsigned)(row * 128 + seg * 16));
            const size_t src = rb + (size_t)row * E_ + seg * 8;
            CP16(stb + sw,          Kh + src);
            CP16(stb + 8192 + sw,   Kl + src);
            CP16(stb + 16384 + sw,  Vh + src);
            CP16(stb + 24576 + sw,  Vl + src);
        }
        CP_COMMIT();
    };

    // ---- stage Q (bf16 hi/lo, 128 rows) ----
    {
        const size_t rb = ((size_t)(b * S_ + bq)) * E_ + h * 64;
#pragma unroll
        for (int i = 0; i < 4; i++) {
            const int g = tid + i * 256;
            const int row = g >> 3, seg = g & 7;
            const unsigned sw = SW128((unsigned)(row * 128 + seg * 16));
            const size_t src = rb + (size_t)row * E_ + seg * 8;
            CP16(sb + SM_Q + sw,         Qh + src);
            CP16(sb + SM_Q + 16384 + sw, Ql + src);
        }
    }
    stage_kv(0);   // Q rides in group 0 with KV tile 0
    stage_kv(1);

    float accO[8][4];
#pragma unroll
    for (int f = 0; f < 8; f++)
#pragma unroll
        for (int j = 0; j < 4; j++) accO[f][j] = 0.0f;
    float m0 = -1e30f, m1 = -1e30f, l0 = 0.0f, l1 = 0.0f;

    unsigned aQh[4][4], aQl[4][4];

    const unsigned bLoc = ((unsigned)lane & 7) + (((unsigned)lane & 16) >> 1);
    const unsigned bHalf = (((unsigned)lane >> 3) & 1) * 16;
    const unsigned vRowBase = ((unsigned)lane & 7) + ((unsigned)lane & 8);
    const unsigned vHalf = (((unsigned)lane >> 4) & 1) * 16;

    for (int t = 0; t < ntiles; t++) {
        if (t + 1 < ntiles) { CP_WAIT(1); } else { CP_WAIT(0); }
        __syncthreads();          // tile t visible; all warps done with t-1
        if (t + 2 < ntiles) stage_kv(t + 2);

        if (t == 0) {             // load Q fragments once
            const unsigned qrow = (unsigned)((wm + (lane & 15)) * 128);
            const unsigned qhalf = ((unsigned)lane >> 4) * 16;
#pragma unroll
            for (int kc = 0; kc < 4; kc++) {
                const unsigned sw = SW128(qrow + (unsigned)(kc * 32) + qhalf);
                ldsm4(aQh[kc], sb + SM_Q + sw);
                ldsm4(aQl[kc], sb + SM_Q + 16384 + sw);
            }
        }

        const unsigned stb = sb + (unsigned)(t % 3) * KV_STG;
        const int j0 = t * 64;

        // ---- S = Q K^T (3-term split) ----
        float accS[8][4];
#pragma unroll
        for (int f = 0; f < 8; f++)
#pragma unroll
            for (int j = 0; j < 4; j++) accS[f][j] = 0.0f;

#pragma unroll
        for (int kc = 0; kc < 4; kc++) {
#pragma unroll
            for (int ng = 0; ng < 4; ng++) {
                const unsigned row = (unsigned)(ng * 16) + bLoc;
                const unsigned sw = SW128(row * 128 + (unsigned)(kc * 32) + bHalf);
                unsigned kh[4], kl[4];
                ldsm4(kh, stb + sw);
                ldsm4(kl, stb + 8192 + sw);
                mma16816(accS[2 * ng],     aQh[kc], kh[0], kh[1]);
                mma16816(accS[2 * ng + 1], aQh[kc], kh[2], kh[3]);
                mma16816(accS[2 * ng],     aQl[kc], kh[0], kh[1]);
                mma16816(accS[2 * ng + 1], aQl[kc], kh[2], kh[3]);
                mma16816(accS[2 * ng],     aQh[kc], kl[0], kl[1]);
                mma16816(accS[2 * ng + 1], aQh[kc], kl[2], kl[3]);
            }
        }

        const int row0 = bq + wm + (lane >> 2);
        const int row1 = row0 + 8;

        // ---- causal mask ----
        if (j0 + 63 > bq + wm) {
#pragma unroll
            for (int f = 0; f < 8; f++) {
                const int c0 = j0 + f * 8 + (lane & 3) * 2;
                if (c0 > row0)     accS[f][0] = -1e30f;
                if (c0 + 1 > row0) accS[f][1] = -1e30f;
                if (c0 > row1)     accS[f][2] = -1e30f;
                if (c0 + 1 > row1) accS[f][3] = -1e30f;
            }
        }

        // ---- online softmax ----
        float rm0 = -1e30f, rm1 = -1e30f;
#pragma unroll
        for (int f = 0; f < 8; f++) {
            rm0 = fmaxf(rm0, fmaxf(accS[f][0], accS[f][1]));
            rm1 = fmaxf(rm1, fmaxf(accS[f][2], accS[f][3]));
        }
        rm0 = fmaxf(rm0, __shfl_xor_sync(0xFFFFFFFF, rm0, 1));
        rm0 = fmaxf(rm0, __shfl_xor_sync(0xFFFFFFFF, rm0, 2));
        rm1 = fmaxf(rm1, __shfl_xor_sync(0xFFFFFFFF, rm1, 1));
        rm1 = fmaxf(rm1, __shfl_xor_sync(0xFFFFFFFF, rm1, 2));
        const float mn0 = fmaxf(m0, rm0);
        const float mn1 = fmaxf(m1, rm1);
        const float sc0 = exp2p(m0 - mn0);
        const float sc1 = exp2p(m1 - mn1);
        m0 = mn0; m1 = mn1;
        l0 *= sc0; l1 *= sc1;
#pragma unroll
        for (int f = 0; f < 8; f++) {
            accO[f][0] *= sc0; accO[f][1] *= sc0;
            accO[f][2] *= sc1; accO[f][3] *= sc1;
        }

        // ---- P = exp2(S - m); O += P V (3-term split) ----
        float sump0 = 0.0f, sump1 = 0.0f;
#pragma unroll
        for (int kc = 0; kc < 4; kc++) {
            const int f0 = 2 * kc, f1 = 2 * kc + 1;
            const float p00 = exp2p(accS[f0][0] - m0);
            const float p01 = exp2p(accS[f0][1] - m0);
            const float p02 = exp2p(accS[f0][2] - m1);
            const float p03 = exp2p(accS[f0][3] - m1);
            const float p10 = exp2p(accS[f1][0] - m0);
            const float p11 = exp2p(accS[f1][1] - m0);
            const float p12 = exp2p(accS[f1][2] - m1);
            const float p13 = exp2p(accS[f1][3] - m1);
            sump0 += (p00 + p01) + (p10 + p11);
            sump1 += (p02 + p03) + (p12 + p13);
            unsigned ph[4], pl[4];
            split2(p00, p01, ph[0], pl[0]);
            split2(p02, p03, ph[1], pl[1]);
            split2(p10, p11, ph[2], pl[2]);
            split2(p12, p13, ph[3], pl[3]);

            const unsigned vrow = (unsigned)(kc * 16) + vRowBase;
#pragma unroll
            for (int nd = 0; nd < 4; nd++) {
                const unsigned sw = SW128(vrow * 128 + (unsigned)(nd * 32) + vHalf);
                unsigned vh[4], vl[4];
                ldsm4t(vh, stb + 16384 + sw);
                ldsm4t(vl, stb + 24576 + sw);
                mma16816(accO[2 * nd],     ph, vh[0], vh[1]);
                mma16816(accO[2 * nd + 1], ph, vh[2], vh[3]);
                mma16816(accO[2 * nd],     pl, vh[0], vh[1]);
                mma16816(accO[2 * nd + 1], pl, vh[2], vh[3]);
                mma16816(accO[2 * nd],     ph, vl[0], vl[1]);
                mma16816(accO[2 * nd + 1], ph, vl[2], vl[3]);
            }
        }
        l0 += sump0;
        l1 += sump1;
    }

    // ---- finalize ----
    l0 += __shfl_xor_sync(0xFFFFFFFF, l0, 1);
    l0 += __shfl_xor_sync(0xFFFFFFFF, l0, 2);
    l1 += __shfl_xor_sync(0xFFFFFFFF, l1, 1);
    l1 += __shfl_xor_sync(0xFFFFFFFF, l1, 2);
    const float inv0 = 1.0f / l0;
    const float inv1 = 1.0f / l1;

    const int row0 = bq + wm + (lane >> 2);
    float* O0 = O + ((size_t)(b * S_ + row0)) * E_ + h * 64;
    float* O1 = O + ((size_t)(b * S_ + row0 + 8)) * E_ + h * 64;
#pragma unroll
    for (int f = 0; f < 8; f++) {
        const int col = f * 8 + (lane & 3) * 2;
        float2 v0, v1;
        v0.x = accO[f][0] * inv0; v0.y = accO[f][1] * inv0;
        v1.x = accO[f][2] * inv1; v1.y = accO[f][3] * inv1;
        *(float2*)(O0 + col) = v0;
        *(float2*)(O1 + col) = v1;
    }
}

// ============================================================================
// Launch
// ============================================================================
extern "C" void kernel_launch(void* const* d_in, const int* in_sizes, int n_in,
                              void* d_out, int out_size) {
    (void)in_sizes; (void)n_in; (void)out_size;

    const float* q  = (const float*)d_in[0];
    const float* k  = (const float*)d_in[1];
    const float* v  = (const float*)d_in[2];
    const float* Wq = (const float*)d_in[4];
    const float* bq = (const float*)d_in[5];
    const float* Wk = (const float*)d_in[6];
    const float* bk = (const float*)d_in[7];
    const float* Wv = (const float*)d_in[8];
    const float* bv = (const float*)d_in[9];
    const float* Wo = (const float*)d_in[10];
    const float* bo = (const float*)d_in[11];
    float* out = (float*)d_out;

    unsigned short *pQh, *pQl, *pKh, *pKl, *pVh, *pVl;
    float* pC;
    cudaGetSymbolAddress((void**)&pQh, g_Qh);
    cudaGetSymbolAddress((void**)&pQl, g_Ql);
    cudaGetSymbolAddress((void**)&pKh, g_Kh);
    cudaGetSymbolAddress((void**)&pKl, g_Kl);
    cudaGetSymbolAddress((void**)&pVh, g_Vh);
    cudaGetSymbolAddress((void**)&pVl, g_Vl);
    cudaGetSymbolAddress((void**)&pC, g_C);

    cudaFuncSetAttribute(gemm_mma, cudaFuncAttributeMaxDynamicSharedMemorySize,
                         GM_DSMEM);
    cudaFuncSetAttribute(flash_attn_bf16, cudaFuncAttributeMaxDynamicSharedMemorySize,
                         FA_DSMEM);

    const int M = B_ * S_;   // 4096
    const int N = E_;        // 1024
    const int K = E_;        // 1024

    dim3 ggrid(N / 128, M / 128);   // (8, 32)
    dim3 gblk(256);

    gemm_mma<<<ggrid, gblk, GM_DSMEM>>>(q, Wq, bq, nullptr,
                                        (unsigned*)pQh, (unsigned*)pQl, QSC, M, N, K);
    gemm_mma<<<ggrid, gblk, GM_DSMEM>>>(k, Wk, bk, nullptr,
                                        (unsigned*)pKh, (unsigned*)pKl, 1.0f, M, N, K);
    gemm_mma<<<ggrid, gblk, GM_DSMEM>>>(v, Wv, bv, nullptr,
                                        (unsigned*)pVh, (unsigned*)pVl, 1.0f, M, N, K);

    flash_attn_bf16<<<512, 256, FA_DSMEM>>>(pQh, pQl, pKh, pKl, pVh, pVl, pC);

    gemm_mma<<<ggrid, gblk, GM_DSMEM>>>(pC, Wo, bo, out,
                                        nullptr, nullptr, 1.0f, M, N, K);
}

// round 7
// speedup vs baseline: 4.0697x; 1.0326x over previous
#include <cuda_runtime.h>
#include <cuda_bf16.h>
#include <math.h>

#define B_ 2
#define S_ 2048
#define E_ 1024
#define H_ 16
#define D_ 64
#define ME_ (B_ * S_ * E_)   // 4M elements
#define WE_ (E_ * E_)        // 1M elements

// Scratch (allocation-free rule: __device__ globals)
// presplit raw inputs
__device__ unsigned short g_qh[ME_], g_ql[ME_];
__device__ unsigned short g_kh[ME_], g_kl[ME_];
__device__ unsigned short g_vh[ME_], g_vl[ME_];
// presplit weights
__device__ unsigned short g_Wqh[WE_], g_Wql[WE_];
__device__ unsigned short g_Wkh[WE_], g_Wkl[WE_];
__device__ unsigned short g_Wvh[WE_], g_Wvl[WE_];
__device__ unsigned short g_Woh[WE_], g_Wol[WE_];
// projected Q/K/V (split)
__device__ unsigned short g_Qh[ME_], g_Ql[ME_];
__device__ unsigned short g_Kh[ME_], g_Kl[ME_];
__device__ unsigned short g_Vh[ME_], g_Vl[ME_];
// attention context (split)
__device__ unsigned short g_Ch[ME_], g_Cl[ME_];

// ============================================================================
// Helpers
// ============================================================================
__device__ __forceinline__ unsigned smem_u32(const void* p) {
    unsigned a;
    asm("{ .reg .u64 t; cvta.to.shared.u64 t, %1; cvt.u32.u64 %0, t; }"
        : "=r"(a) : "l"(p));
    return a;
}

#define CP16(dst, src) \
    asm volatile("cp.async.cg.shared.global [%0], [%1], 16;" \
                 :: "r"((unsigned)(dst)), "l"(src) : "memory")
#define CP_COMMIT() asm volatile("cp.async.commit_group;" ::: "memory")
#define CP_WAIT(n)  asm volatile("cp.async.wait_group %0;" :: "n"(n) : "memory")

__device__ __forceinline__ void ldsm4(unsigned* r, unsigned addr) {
    asm volatile("ldmatrix.sync.aligned.m8n8.x4.shared.b16 {%0,%1,%2,%3}, [%4];"
                 : "=r"(r[0]), "=r"(r[1]), "=r"(r[2]), "=r"(r[3]) : "r"(addr));
}
__device__ __forceinline__ void ldsm4t(unsigned* r, unsigned addr) {
    asm volatile("ldmatrix.sync.aligned.m8n8.x4.trans.shared.b16 {%0,%1,%2,%3}, [%4];"
                 : "=r"(r[0]), "=r"(r[1]), "=r"(r[2]), "=r"(r[3]) : "r"(addr));
}

__device__ __forceinline__ void mma16816(float* d, const unsigned* a,
                                         unsigned b0, unsigned b1) {
    asm volatile(
        "mma.sync.aligned.m16n8k16.row.col.f32.bf16.bf16.f32 "
        "{%0,%1,%2,%3}, {%4,%5,%6,%7}, {%8,%9}, {%0,%1,%2,%3};"
        : "+f"(d[0]), "+f"(d[1]), "+f"(d[2]), "+f"(d[3])
        : "r"(a[0]), "r"(a[1]), "r"(a[2]), "r"(a[3]), "r"(b0), "r"(b1));
}

__device__ __forceinline__ unsigned pack_bf2(float flo, float fhi) {
    unsigned r;
    asm("cvt.rn.bf16x2.f32 %0, %1, %2;" : "=r"(r) : "f"(fhi), "f"(flo));
    return r;
}
__device__ __forceinline__ void split2(float x0, float x1, unsigned& hi, unsigned& lo) {
    hi = pack_bf2(x0, x1);
    float h0 = __uint_as_float(hi << 16);
    float h1 = __uint_as_float(hi & 0xFFFF0000u);
    lo = pack_bf2(x0 - h0, x1 - h1);
}

// fast 2^t on the fma pipe (t <= 0), err ~2e-6
__device__ __forceinline__ float exp2p(float t) {
    t = fmaxf(t, -126.0f);
    float z = t + 12582912.0f;
    float r = t - (z - 12582912.0f);
    float p = 0.0013333558f;
    p = fmaf(p, r, 0.0096181291f);
    p = fmaf(p, r, 0.0555041087f);
    p = fmaf(p, r, 0.2402265069f);
    p = fmaf(p, r, 0.6931471806f);
    p = fmaf(p, r, 1.0f);
    unsigned eb = (__float_as_uint(z) << 23) + 0x3F800000u;
    return __uint_as_float(eb) * p;
}

#define SW128(o) ((o) ^ (((o) >> 3) & 0x70))
#define QSC 0.1803368801111244f   // 0.125 * log2(e)

// ============================================================================
// Pre-split: fp32 -> bf16 hi/lo (vectorized)
// ============================================================================
__global__ __launch_bounds__(256)
void presplit(const float* __restrict__ X, unsigned* __restrict__ Hx,
              unsigned* __restrict__ Lx, int n4) {
    const int i = blockIdx.x * 256 + threadIdx.x;
    if (i < n4) {
        const float4 x = ((const float4*)X)[i];
        unsigned h0, l0, h1, l1;
        split2(x.x, x.y, h0, l0);
        split2(x.z, x.w, h1, l1);
        ((uint2*)Hx)[i] = make_uint2(h0, h1);
        ((uint2*)Lx)[i] = make_uint2(l0, l1);
    }
}

// ============================================================================
// GEMM (NT) on pre-split bf16: Y = A @ W^T + bias.
// Block 128x128, BK=32, 256 threads (8 warps x 32m x 64n), 3-stage cp.async.
// Stage: [Ah 8K | Al 8K | Wh 8K | Wl 8K] = 32KB; piece = 128 rows x 64B.
// Epilogue: fp32 C (Hout==nullptr) or scaled bf16 hi/lo split store.
// ============================================================================
#define PIECE 8192
#define GSTG 32768
#define GM_DSMEM (3 * GSTG)

__global__ __launch_bounds__(256, 1)
void gemm_bf16(const unsigned short* __restrict__ Ah,
               const unsigned short* __restrict__ Al,
               const unsigned short* __restrict__ Wh,
               const unsigned short* __restrict__ Wl,
               const float* __restrict__ bias, float* __restrict__ C,
               unsigned* __restrict__ Hout, unsigned* __restrict__ Lout,
               float oscale, int M, int N, int K) {
    extern __shared__ char smem_raw[];
    const unsigned sbase = smem_u32(smem_raw);
    const int tid = threadIdx.x;
    const int lane = tid & 31;
    const int wid = tid >> 5;
    const int bm = blockIdx.y * 128;
    const int bn = blockIdx.x * 128;

    // staging: 512 x 16B per 8K piece; thread -> 2 groups
    auto stage = [&](int c) {
        const unsigned stb = sbase + (unsigned)(c % 3) * GSTG;
#pragma unroll
        for (int i = 0; i < 2; i++) {
            const int g = tid + i * 256;
            const int row = g >> 2, c16 = g & 3;
            const unsigned dst = (unsigned)(row * 64) +
                                 ((((unsigned)c16) ^ (((unsigned)row >> 1) & 3)) << 4);
            const size_t sA = (size_t)(bm + row) * K + c * 32 + c16 * 8;
            const size_t sW = (size_t)(bn + row) * K + c * 32 + c16 * 8;
            CP16(stb + dst,         Ah + sA);
            CP16(stb + PIECE + dst, Al + sA);
            CP16(stb + 2 * PIECE + dst, Wh + sW);
            CP16(stb + 3 * PIECE + dst, Wl + sW);
        }
        CP_COMMIT();
    };

    // compute mapping (validated R3 layout)
    const int wm = (wid & 3) * 32;
    const int wn = (wid >> 2) * 64;
    const unsigned aRow = (unsigned)((wm + (lane & 15)) * 64);
    const unsigned aG = (((unsigned)lane & 15) >> 1) & 3;
    const unsigned aHalf = (unsigned)lane >> 4;
    const unsigned bLocal = ((unsigned)lane & 7) + (((unsigned)lane & 16) >> 1);
    const unsigned bRow = (unsigned)((wn + (int)bLocal) * 64);
    const unsigned bG = (bLocal >> 1) & 3;
    const unsigned bHalf = ((unsigned)lane >> 3) & 1;

    float acc[2][8][4];
#pragma unroll
    for (int i = 0; i < 2; i++)
#pragma unroll
        for (int j = 0; j < 8; j++)
#pragma unroll
            for (int t = 0; t < 4; t++) acc[i][j][t] = 0.0f;

    auto compute = [&](unsigned stg) {
#pragma unroll
        for (int ks = 0; ks < 2; ks++) {
            unsigned ah0[4], ah1[4], al0[4], al1[4];
            const unsigned aoffs = (((unsigned)(2 * ks) + aHalf) ^ aG) << 4;
            ldsm4(ah0, stg + aRow + aoffs);
            ldsm4(ah1, stg + aRow + 1024 + aoffs);
            ldsm4(al0, stg + PIECE + aRow + aoffs);
            ldsm4(al1, stg + PIECE + aRow + 1024 + aoffs);
            const unsigned boffs = (((unsigned)(2 * ks) + bHalf) ^ bG) << 4;
#pragma unroll
            for (int ng = 0; ng < 4; ng++) {
                unsigned bh[4], bl[4];
                ldsm4(bh, stg + 2 * PIECE + bRow + ng * 1024 + boffs);
                ldsm4(bl, stg + 3 * PIECE + bRow + ng * 1024 + boffs);
                mma16816(acc[0][2 * ng],     ah0, bh[0], bh[1]);
                mma16816(acc[0][2 * ng + 1], ah0, bh[2], bh[3]);
                mma16816(acc[1][2 * ng],     ah1, bh[0], bh[1]);
                mma16816(acc[1][2 * ng + 1], ah1, bh[2], bh[3]);
                mma16816(acc[0][2 * ng],     ah0, bl[0], bl[1]);
                mma16816(acc[0][2 * ng + 1], ah0, bl[2], bl[3]);
                mma16816(acc[1][2 * ng],     ah1, bl[0], bl[1]);
                mma16816(acc[1][2 * ng + 1], ah1, bl[2], bl[3]);
                mma16816(acc[0][2 * ng],     al0, bh[0], bh[1]);
                mma16816(acc[0][2 * ng + 1], al0, bh[2], bh[3]);
                mma16816(acc[1][2 * ng],     al1, bh[0], bh[1]);
                mma16816(acc[1][2 * ng + 1], al1, bh[2], bh[3]);
            }
        }
    };

    const int nchunk = K / 32;   // 32
    stage(0);
    stage(1);
    for (int c = 0; c < nchunk; c++) {
        if (c + 1 < nchunk) { CP_WAIT(1); } else { CP_WAIT(0); }
        __syncthreads();
        if (c + 2 < nchunk) stage(c + 2);
        compute(sbase + (unsigned)(c % 3) * GSTG);
    }

    // ---- epilogue ----
    const int r0 = bm + wm + (lane >> 2);
    const int c0 = bn + wn + (lane & 3) * 2;
    if (Hout) {
#pragma unroll
        for (int mf = 0; mf < 2; mf++) {
#pragma unroll
            for (int ng = 0; ng < 8; ng++) {
                const int row = r0 + mf * 16;
                const int col = c0 + ng * 8;
                const float2 bb = *(const float2*)(bias + col);
                unsigned h0, l0, h1, l1;
                split2((acc[mf][ng][0] + bb.x) * oscale,
                       (acc[mf][ng][1] + bb.y) * oscale, h0, l0);
                split2((acc[mf][ng][2] + bb.x) * oscale,
                       (acc[mf][ng][3] + bb.y) * oscale, h1, l1);
                const size_t i0 = (size_t)row * (N / 2) + col / 2;
                const size_t i1 = (size_t)(row + 8) * (N / 2) + col / 2;
                Hout[i0] = h0; Lout[i0] = l0;
                Hout[i1] = h1; Lout[i1] = l1;
            }
        }
    } else {
#pragma unroll
        for (int mf = 0; mf < 2; mf++) {
#pragma unroll
            for (int ng = 0; ng < 8; ng++) {
                const int row = r0 + mf * 16;
                const int col = c0 + ng * 8;
                const float2 bb = *(const float2*)(bias + col);
                float2 v0, v1;
                v0.x = acc[mf][ng][0] + bb.x;
                v0.y = acc[mf][ng][1] + bb.y;
                v1.x = acc[mf][ng][2] + bb.x;
                v1.y = acc[mf][ng][3] + bb.y;
                *(float2*)(C + (size_t)row * N + col) = v0;
                *(float2*)(C + (size_t)(row + 8) * N + col) = v1;
            }
        }
    }
}

// ============================================================================
// Flash attention on pre-split bf16 (causal, base-2 softmax).
// Output written pre-split (hi/lo) for the out-projection GEMM.
// ============================================================================
#define FA_DSMEM 131072
#define KV_STG 32768
#define SM_Q 98304

__global__ __launch_bounds__(256, 1)
void flash_attn_bf16(const unsigned short* __restrict__ Qh,
                     const unsigned short* __restrict__ Ql,
                     const unsigned short* __restrict__ Kh,
                     const unsigned short* __restrict__ Kl,
                     const unsigned short* __restrict__ Vh,
                     const unsigned short* __restrict__ Vl,
                     unsigned short* __restrict__ Oh,
                     unsigned short* __restrict__ Ol) {
    extern __shared__ char sm[];
    const unsigned sb = smem_u32(sm);
    const int tid = threadIdx.x;
    const int lane = tid & 31;
    const int wid = tid >> 5;

    // LPT remap: heavy (large bx) CTAs first
    const int idx = blockIdx.x;
    const int bx = 15 - (idx >> 5);
    const int rem = idx & 31;
    const int h = rem & 15;
    const int b = rem >> 4;
    const int bq = bx * 128;
    const int wm = wid * 16;
    const int ntiles = 2 * bx + 2;

    auto stage_kv = [&](int t) {
        const unsigned stb = sb + (unsigned)(t % 3) * KV_STG;
        const int j0 = t * 64;
        const size_t rb = ((size_t)(b * S_ + j0)) * E_ + h * 64;
#pragma unroll
        for (int i = 0; i < 2; i++) {
            const int g = tid + i * 256;
            const int row = g >> 3, seg = g & 7;
            const unsigned sw = SW128((unsigned)(row * 128 + seg * 16));
            const size_t src = rb + (size_t)row * E_ + seg * 8;
            CP16(stb + sw,          Kh + src);
            CP16(stb + 8192 + sw,   Kl + src);
            CP16(stb + 16384 + sw,  Vh + src);
            CP16(stb + 24576 + sw,  Vl + src);
        }
        CP_COMMIT();
    };

    {
        const size_t rb = ((size_t)(b * S_ + bq)) * E_ + h * 64;
#pragma unroll
        for (int i = 0; i < 4; i++) {
            const int g = tid + i * 256;
            const int row = g >> 3, seg = g & 7;
            const unsigned sw = SW128((unsigned)(row * 128 + seg * 16));
            const size_t src = rb + (size_t)row * E_ + seg * 8;
            CP16(sb + SM_Q + sw,         Qh + src);
            CP16(sb + SM_Q + 16384 + sw, Ql + src);
        }
    }
    stage_kv(0);
    stage_kv(1);

    float accO[8][4];
#pragma unroll
    for (int f = 0; f < 8; f++)
#pragma unroll
        for (int j = 0; j < 4; j++) accO[f][j] = 0.0f;
    float m0 = -1e30f, m1 = -1e30f, l0 = 0.0f, l1 = 0.0f;

    unsigned aQh[4][4], aQl[4][4];

    const unsigned bLoc = ((unsigned)lane & 7) + (((unsigned)lane & 16) >> 1);
    const unsigned bHalf = (((unsigned)lane >> 3) & 1) * 16;
    const unsigned vRowBase = ((unsigned)lane & 7) + ((unsigned)lane & 8);
    const unsigned vHalf = (((unsigned)lane >> 4) & 1) * 16;

    for (int t = 0; t < ntiles; t++) {
        if (t + 1 < ntiles) { CP_WAIT(1); } else { CP_WAIT(0); }
        __syncthreads();
        if (t + 2 < ntiles) stage_kv(t + 2);

        if (t == 0) {
            const unsigned qrow = (unsigned)((wm + (lane & 15)) * 128);
            const unsigned qhalf = ((unsigned)lane >> 4) * 16;
#pragma unroll
            for (int kc = 0; kc < 4; kc++) {
                const unsigned sw = SW128(qrow + (unsigned)(kc * 32) + qhalf);
                ldsm4(aQh[kc], sb + SM_Q + sw);
                ldsm4(aQl[kc], sb + SM_Q + 16384 + sw);
            }
        }

        const unsigned stb = sb + (unsigned)(t % 3) * KV_STG;
        const int j0 = t * 64;

        float accS[8][4];
#pragma unroll
        for (int f = 0; f < 8; f++)
#pragma unroll
            for (int j = 0; j < 4; j++) accS[f][j] = 0.0f;

#pragma unroll
        for (int kc = 0; kc < 4; kc++) {
#pragma unroll
            for (int ng = 0; ng < 4; ng++) {
                const unsigned row = (unsigned)(ng * 16) + bLoc;
                const unsigned sw = SW128(row * 128 + (unsigned)(kc * 32) + bHalf);
                unsigned kh[4], kl[4];
                ldsm4(kh, stb + sw);
                ldsm4(kl, stb + 8192 + sw);
                mma16816(accS[2 * ng],     aQh[kc], kh[0], kh[1]);
                mma16816(accS[2 * ng + 1], aQh[kc], kh[2], kh[3]);
                mma16816(accS[2 * ng],     aQl[kc], kh[0], kh[1]);
                mma16816(accS[2 * ng + 1], aQl[kc], kh[2], kh[3]);
                mma16816(accS[2 * ng],     aQh[kc], kl[0], kl[1]);
                mma16816(accS[2 * ng + 1], aQh[kc], kl[2], kl[3]);
            }
        }

        const int row0 = bq + wm + (lane >> 2);
        const int row1 = row0 + 8;

        if (j0 + 63 > bq + wm) {
#pragma unroll
            for (int f = 0; f < 8; f++) {
                const int c0 = j0 + f * 8 + (lane & 3) * 2;
                if (c0 > row0)     accS[f][0] = -1e30f;
                if (c0 + 1 > row0) accS[f][1] = -1e30f;
                if (c0 > row1)     accS[f][2] = -1e30f;
                if (c0 + 1 > row1) accS[f][3] = -1e30f;
            }
        }

        float rm0 = -1e30f, rm1 = -1e30f;
#pragma unroll
        for (int f = 0; f < 8; f++) {
            rm0 = fmaxf(rm0, fmaxf(accS[f][0], accS[f][1]));
            rm1 = fmaxf(rm1, fmaxf(accS[f][2], accS[f][3]));
        }
        rm0 = fmaxf(rm0, __shfl_xor_sync(0xFFFFFFFF, rm0, 1));
        rm0 = fmaxf(rm0, __shfl_xor_sync(0xFFFFFFFF, rm0, 2));
        rm1 = fmaxf(rm1, __shfl_xor_sync(0xFFFFFFFF, rm1, 1));
        rm1 = fmaxf(rm1, __shfl_xor_sync(0xFFFFFFFF, rm1, 2));
        const float mn0 = fmaxf(m0, rm0);
        const float mn1 = fmaxf(m1, rm1);
        const float sc0 = exp2p(m0 - mn0);
        const float sc1 = exp2p(m1 - mn1);
        m0 = mn0; m1 = mn1;
        l0 *= sc0; l1 *= sc1;
#pragma unroll
        for (int f = 0; f < 8; f++) {
            accO[f][0] *= sc0; accO[f][1] *= sc0;
            accO[f][2] *= sc1; accO[f][3] *= sc1;
        }

        float sump0 = 0.0f, sump1 = 0.0f;
#pragma unroll
        for (int kc = 0; kc < 4; kc++) {
            const int f0 = 2 * kc, f1 = 2 * kc + 1;
            const float p00 = exp2p(accS[f0][0] - m0);
            const float p01 = exp2p(accS[f0][1] - m0);
            const float p02 = exp2p(accS[f0][2] - m1);
            const float p03 = exp2p(accS[f0][3] - m1);
            const float p10 = exp2p(accS[f1][0] - m0);
            const float p11 = exp2p(accS[f1][1] - m0);
            const float p12 = exp2p(accS[f1][2] - m1);
            const float p13 = exp2p(accS[f1][3] - m1);
            sump0 += (p00 + p01) + (p10 + p11);
            sump1 += (p02 + p03) + (p12 + p13);
            unsigned ph[4], pl[4];
            split2(p00, p01, ph[0], pl[0]);
            split2(p02, p03, ph[1], pl[1]);
            split2(p10, p11, ph[2], pl[2]);
            split2(p12, p13, ph[3], pl[3]);

            const unsigned vrow = (unsigned)(kc * 16) + vRowBase;
#pragma unroll
            for (int nd = 0; nd < 4; nd++) {
                const unsigned sw = SW128(vrow * 128 + (unsigned)(nd * 32) + vHalf);
                unsigned vh[4], vl[4];
                ldsm4t(vh, stb + 16384 + sw);
                ldsm4t(vl, stb + 24576 + sw);
                mma16816(accO[2 * nd],     ph, vh[0], vh[1]);
                mma16816(accO[2 * nd + 1], ph, vh[2], vh[3]);
                mma16816(accO[2 * nd],     pl, vh[0], vh[1]);
                mma16816(accO[2 * nd + 1], pl, vh[2], vh[3]);
                mma16816(accO[2 * nd],     ph, vl[0], vl[1]);
                mma16816(accO[2 * nd + 1], ph, vl[2], vl[3]);
            }
        }
        l0 += sump0;
        l1 += sump1;
    }

    // ---- finalize: write pre-split O ----
    l0 += __shfl_xor_sync(0xFFFFFFFF, l0, 1);
    l0 += __shfl_xor_sync(0xFFFFFFFF, l0, 2);
    l1 += __shfl_xor_sync(0xFFFFFFFF, l1, 1);
    l1 += __shfl_xor_sync(0xFFFFFFFF, l1, 2);
    const float inv0 = 1.0f / l0;
    const float inv1 = 1.0f / l1;

    const int row0 = bq + wm + (lane >> 2);
    unsigned* OhU = (unsigned*)Oh;
    unsigned* OlU = (unsigned*)Ol;
#pragma unroll
    for (int f = 0; f < 8; f++) {
        const int col = f * 8 + (lane & 3) * 2;
        const size_t i0 = ((size_t)(b * S_ + row0)) * (E_ / 2) + h * 32 + col / 2;
        const size_t i1 = ((size_t)(b * S_ + row0 + 8)) * (E_ / 2) + h * 32 + col / 2;
        unsigned h0, l0u, h1, l1u;
        split2(accO[f][0] * inv0, accO[f][1] * inv0, h0, l0u);
        split2(accO[f][2] * inv1, accO[f][3] * inv1, h1, l1u);
        OhU[i0] = h0; OlU[i0] = l0u;
        OhU[i1] = h1; OlU[i1] = l1u;
    }
}

// ============================================================================
// Launch
// ============================================================================
extern "C" void kernel_launch(void* const* d_in, const int* in_sizes, int n_in,
                              void* d_out, int out_size) {
    (void)in_sizes; (void)n_in; (void)out_size;

    const float* q  = (const float*)d_in[0];
    const float* k  = (const float*)d_in[1];
    const float* v  = (const float*)d_in[2];
    const float* Wq = (const float*)d_in[4];
    const float* bq = (const float*)d_in[5];
    const float* Wk = (const float*)d_in[6];
    const float* bk = (const float*)d_in[7];
    const float* Wv = (const float*)d_in[8];
    const float* bv = (const float*)d_in[9];
    const float* Wo = (const float*)d_in[10];
    const float* bo = (const float*)d_in[11];
    float* out = (float*)d_out;

    unsigned short *qh, *ql, *kh, *kl, *vh, *vl;
    unsigned short *Wqh, *Wql, *Wkh, *Wkl, *Wvh, *Wvl, *Woh, *Wol;
    unsigned short *Qh, *Ql, *Kh, *Kl, *Vh, *Vl, *Ch, *Cl;
    cudaGetSymbolAddress((void**)&qh, g_qh);   cudaGetSymbolAddress((void**)&ql, g_ql);
    cudaGetSymbolAddress((void**)&kh, g_kh);   cudaGetSymbolAddress((void**)&kl, g_kl);
    cudaGetSymbolAddress((void**)&vh, g_vh);   cudaGetSymbolAddress((void**)&vl, g_vl);
    cudaGetSymbolAddress((void**)&Wqh, g_Wqh); cudaGetSymbolAddress((void**)&Wql, g_Wql);
    cudaGetSymbolAddress((void**)&Wkh, g_Wkh); cudaGetSymbolAddress((void**)&Wkl, g_Wkl);
    cudaGetSymbolAddress((void**)&Wvh, g_Wvh); cudaGetSymbolAddress((void**)&Wvl, g_Wvl);
    cudaGetSymbolAddress((void**)&Woh, g_Woh); cudaGetSymbolAddress((void**)&Wol, g_Wol);
    cudaGetSymbolAddress((void**)&Qh, g_Qh);   cudaGetSymbolAddress((void**)&Ql, g_Ql);
    cudaGetSymbolAddress((void**)&Kh, g_Kh);   cudaGetSymbolAddress((void**)&Kl, g_Kl);
    cudaGetSymbolAddress((void**)&Vh, g_Vh);   cudaGetSymbolAddress((void**)&Vl, g_Vl);
    cudaGetSymbolAddress((void**)&Ch, g_Ch);   cudaGetSymbolAddress((void**)&Cl, g_Cl);

    cudaFuncSetAttribute(gemm_bf16, cudaFuncAttributeMaxDynamicSharedMemorySize,
                         GM_DSMEM);
    cudaFuncSetAttribute(flash_attn_bf16, cudaFuncAttributeMaxDynamicSharedMemorySize,
                         FA_DSMEM);

    const int M = B_ * S_;   // 4096
    const int N = E_;        // 1024
    const int K = E_;        // 1024

    // ---- pre-split inputs + weights ----
    const int mn4 = ME_ / 4, wn4 = WE_ / 4;
    presplit<<<mn4 / 256, 256>>>(q, (unsigned*)qh, (unsigned*)ql, mn4);
    presplit<<<mn4 / 256, 256>>>(k, (unsigned*)kh, (unsigned*)kl, mn4);
    presplit<<<mn4 / 256, 256>>>(v, (unsigned*)vh, (unsigned*)vl, mn4);
    presplit<<<wn4 / 256, 256>>>(Wq, (unsigned*)Wqh, (unsigned*)Wql, wn4);
    presplit<<<wn4 / 256, 256>>>(Wk, (unsigned*)Wkh, (unsigned*)Wkl, wn4);
    presplit<<<wn4 / 256, 256>>>(Wv, (unsigned*)Wvh, (unsigned*)Wvl, wn4);
    presplit<<<wn4 / 256, 256>>>(Wo, (unsigned*)Woh, (unsigned*)Wol, wn4);

    dim3 ggrid(N / 128, M / 128);   // (8, 32)
    dim3 gblk(256);

    gemm_bf16<<<ggrid, gblk, GM_DSMEM>>>(qh, ql, Wqh, Wql, bq, nullptr,
                                         (unsigned*)Qh, (unsigned*)Ql, QSC, M, N, K);
    gemm_bf16<<<ggrid, gblk, GM_DSMEM>>>(kh, kl, Wkh, Wkl, bk, nullptr,
                                         (unsigned*)Kh, (unsigned*)Kl, 1.0f, M, N, K);
    gemm_bf16<<<ggrid, gblk, GM_DSMEM>>>(vh, vl, Wvh, Wvl, bv, nullptr,
                                         (unsigned*)Vh, (unsigned*)Vl, 1.0f, M, N, K);

    flash_attn_bf16<<<512, 256, FA_DSMEM>>>(Qh, Ql, Kh, Kl, Vh, Vl, Ch, Cl);

    gemm_bf16<<<ggrid, gblk, GM_DSMEM>>>(Ch, Cl, Woh, Wol, bo, out,
                                         nullptr, nullptr, 1.0f, M, N, K);
}

// round 8
// speedup vs baseline: 4.5058x; 1.1071x over previous
#include <cuda_runtime.h>
#include <cuda_bf16.h>
#include <math.h>

#define B_ 2
#define S_ 2048
#define E_ 1024
#define H_ 16
#define D_ 64
#define ME_ (B_ * S_ * E_)   // 4M elements
#define WE_ (E_ * E_)        // 1M elements

// Scratch (allocation-free rule: __device__ globals)
__device__ unsigned short g_qh[ME_], g_ql[ME_];
__device__ unsigned short g_kh[ME_], g_kl[ME_];
__device__ unsigned short g_vh[ME_], g_vl[ME_];
__device__ unsigned short g_Wqh[WE_], g_Wql[WE_];
__device__ unsigned short g_Wkh[WE_], g_Wkl[WE_];
__device__ unsigned short g_Wvh[WE_], g_Wvl[WE_];
__device__ unsigned short g_Woh[WE_], g_Wol[WE_];
__device__ unsigned short g_Qh[ME_], g_Ql[ME_];
__device__ unsigned short g_Kh[ME_], g_Kl[ME_];
__device__ unsigned short g_Vh[ME_], g_Vl[ME_];
__device__ unsigned short g_Ch[ME_], g_Cl[ME_];

// ============================================================================
// Helpers
// ============================================================================
__device__ __forceinline__ unsigned smem_u32(const void* p) {
    unsigned a;
    asm("{ .reg .u64 t; cvta.to.shared.u64 t, %1; cvt.u32.u64 %0, t; }"
        : "=r"(a) : "l"(p));
    return a;
}

#define CP16(dst, src) \
    asm volatile("cp.async.cg.shared.global [%0], [%1], 16;" \
                 :: "r"((unsigned)(dst)), "l"(src) : "memory")
#define CP_COMMIT() asm volatile("cp.async.commit_group;" ::: "memory")
#define CP_WAIT(n)  asm volatile("cp.async.wait_group %0;" :: "n"(n) : "memory")

__device__ __forceinline__ void ldsm4(unsigned* r, unsigned addr) {
    asm volatile("ldmatrix.sync.aligned.m8n8.x4.shared.b16 {%0,%1,%2,%3}, [%4];"
                 : "=r"(r[0]), "=r"(r[1]), "=r"(r[2]), "=r"(r[3]) : "r"(addr));
}
__device__ __forceinline__ void ldsm4t(unsigned* r, unsigned addr) {
    asm volatile("ldmatrix.sync.aligned.m8n8.x4.trans.shared.b16 {%0,%1,%2,%3}, [%4];"
                 : "=r"(r[0]), "=r"(r[1]), "=r"(r[2]), "=r"(r[3]) : "r"(addr));
}

__device__ __forceinline__ void mma16816(float* d, const unsigned* a,
                                         unsigned b0, unsigned b1) {
    asm volatile(
        "mma.sync.aligned.m16n8k16.row.col.f32.bf16.bf16.f32 "
        "{%0,%1,%2,%3}, {%4,%5,%6,%7}, {%8,%9}, {%0,%1,%2,%3};"
        : "+f"(d[0]), "+f"(d[1]), "+f"(d[2]), "+f"(d[3])
        : "r"(a[0]), "r"(a[1]), "r"(a[2]), "r"(a[3]), "r"(b0), "r"(b1));
}

__device__ __forceinline__ unsigned pack_bf2(float flo, float fhi) {
    unsigned r;
    asm("cvt.rn.bf16x2.f32 %0, %1, %2;" : "=r"(r) : "f"(fhi), "f"(flo));
    return r;
}
__device__ __forceinline__ void split2(float x0, float x1, unsigned& hi, unsigned& lo) {
    hi = pack_bf2(x0, x1);
    float h0 = __uint_as_float(hi << 16);
    float h1 = __uint_as_float(hi & 0xFFFF0000u);
    lo = pack_bf2(x0 - h0, x1 - h1);
}

// fast 2^t on the fma pipe (t <= 0), err ~2e-6
__device__ __forceinline__ float exp2p(float t) {
    t = fmaxf(t, -126.0f);
    float z = t + 12582912.0f;
    float r = t - (z - 12582912.0f);
    float p = 0.0013333558f;
    p = fmaf(p, r, 0.0096181291f);
    p = fmaf(p, r, 0.0555041087f);
    p = fmaf(p, r, 0.2402265069f);
    p = fmaf(p, r, 0.6931471806f);
    p = fmaf(p, r, 1.0f);
    unsigned eb = (__float_as_uint(z) << 23) + 0x3F800000u;
    return __uint_as_float(eb) * p;
}

#define SW128(o) ((o) ^ (((o) >> 3) & 0x70))
#define QSC 0.1803368801111244f   // 0.125 * log2(e)

// ============================================================================
// Pre-split: fp32 -> bf16 hi/lo
// ============================================================================
__global__ __launch_bounds__(256)
void presplit(const float* __restrict__ X, unsigned* __restrict__ Hx,
              unsigned* __restrict__ Lx, int n4) {
    const int i = blockIdx.x * 256 + threadIdx.x;
    if (i < n4) {
        const float4 x = ((const float4*)X)[i];
        unsigned h0, l0, h1, l1;
        split2(x.x, x.y, h0, l0);
        split2(x.z, x.w, h1, l1);
        ((uint2*)Hx)[i] = make_uint2(h0, h1);
        ((uint2*)Lx)[i] = make_uint2(l0, l1);
    }
}

// ============================================================================
// GEMM core (NT) on pre-split bf16, 2-stage ring, occupancy 2.
// Block 128x128, BK=32, 256 threads (8 warps x 32m x 64n).
// Stage: [Ah 8K | Al 8K | Wh 8K | Wl 8K] = 32KB x 2 stages = 64KB.
// ============================================================================
#define PIECE 8192
#define GSTG 32768
#define GM_DSMEM (2 * GSTG)

struct GemmOps {
    const unsigned short *Ah, *Al, *Wh, *Wl;
    const float* bias;
    float* C;                 // fp32 out (null if split out)
    unsigned *Hout, *Lout;    // split out
    float oscale;
};

__device__ __forceinline__ void gemm_body(const GemmOps& op, int bm, int bn,
                                          unsigned sbase, int M, int N, int K) {
    const int tid = threadIdx.x;
    const int lane = tid & 31;
    const int wid = tid >> 5;

    auto stage = [&](int c) {
        const unsigned stb = sbase + (unsigned)(c & 1) * GSTG;
#pragma unroll
        for (int i = 0; i < 2; i++) {
            const int g = tid + i * 256;
            const int row = g >> 2, c16 = g & 3;
            const unsigned dst = (unsigned)(row * 64) +
                                 ((((unsigned)c16) ^ (((unsigned)row >> 1) & 3)) << 4);
            const size_t sA = (size_t)(bm + row) * K + c * 32 + c16 * 8;
            const size_t sW = (size_t)(bn + row) * K + c * 32 + c16 * 8;
            CP16(stb + dst,             op.Ah + sA);
            CP16(stb + PIECE + dst,     op.Al + sA);
            CP16(stb + 2 * PIECE + dst, op.Wh + sW);
            CP16(stb + 3 * PIECE + dst, op.Wl + sW);
        }
        CP_COMMIT();
    };

    const int wm = (wid & 3) * 32;
    const int wn = (wid >> 2) * 64;
    const unsigned aRow = (unsigned)((wm + (lane & 15)) * 64);
    const unsigned aG = (((unsigned)lane & 15) >> 1) & 3;
    const unsigned aHalf = (unsigned)lane >> 4;
    const unsigned bLocal = ((unsigned)lane & 7) + (((unsigned)lane & 16) >> 1);
    const unsigned bRow = (unsigned)((wn + (int)bLocal) * 64);
    const unsigned bG = (bLocal >> 1) & 3;
    const unsigned bHalf = ((unsigned)lane >> 3) & 1;

    float acc[2][8][4];
#pragma unroll
    for (int i = 0; i < 2; i++)
#pragma unroll
        for (int j = 0; j < 8; j++)
#pragma unroll
            for (int t = 0; t < 4; t++) acc[i][j][t] = 0.0f;

    auto compute = [&](unsigned stg) {
#pragma unroll
        for (int ks = 0; ks < 2; ks++) {
            unsigned ah0[4], ah1[4], al0[4], al1[4];
            const unsigned aoffs = (((unsigned)(2 * ks) + aHalf) ^ aG) << 4;
            ldsm4(ah0, stg + aRow + aoffs);
            ldsm4(ah1, stg + aRow + 1024 + aoffs);
            ldsm4(al0, stg + PIECE + aRow + aoffs);
            ldsm4(al1, stg + PIECE + aRow + 1024 + aoffs);
            const unsigned boffs = (((unsigned)(2 * ks) + bHalf) ^ bG) << 4;
#pragma unroll
            for (int ng = 0; ng < 4; ng++) {
                unsigned bh[4], bl[4];
                ldsm4(bh, stg + 2 * PIECE + bRow + ng * 1024 + boffs);
                ldsm4(bl, stg + 3 * PIECE + bRow + ng * 1024 + boffs);
                mma16816(acc[0][2 * ng],     ah0, bh[0], bh[1]);
                mma16816(acc[0][2 * ng + 1], ah0, bh[2], bh[3]);
                mma16816(acc[1][2 * ng],     ah1, bh[0], bh[1]);
                mma16816(acc[1][2 * ng + 1], ah1, bh[2], bh[3]);
                mma16816(acc[0][2 * ng],     ah0, bl[0], bl[1]);
                mma16816(acc[0][2 * ng + 1], ah0, bl[2], bl[3]);
                mma16816(acc[1][2 * ng],     ah1, bl[0], bl[1]);
                mma16816(acc[1][2 * ng + 1], ah1, bl[2], bl[3]);
                mma16816(acc[0][2 * ng],     al0, bh[0], bh[1]);
                mma16816(acc[0][2 * ng + 1], al0, bh[2], bh[3]);
                mma16816(acc[1][2 * ng],     al1, bh[0], bh[1]);
                mma16816(acc[1][2 * ng + 1], al1, bh[2], bh[3]);
            }
        }
    };

    const int nchunk = K / 32;   // 32
    stage(0);
    stage(1);
    for (int c = 0; c < nchunk; c++) {
        if (c + 1 < nchunk) { CP_WAIT(1); } else { CP_WAIT(0); }
        __syncthreads();
        compute(sbase + (unsigned)(c & 1) * GSTG);
        __syncthreads();
        if (c + 2 < nchunk) stage(c + 2);
    }

    // ---- epilogue ----
    const int r0 = bm + wm + (lane >> 2);
    const int c0 = bn + wn + (lane & 3) * 2;
    if (op.Hout) {
#pragma unroll
        for (int mf = 0; mf < 2; mf++) {
#pragma unroll
            for (int ng = 0; ng < 8; ng++) {
                const int row = r0 + mf * 16;
                const int col = c0 + ng * 8;
                const float2 bb = *(const float2*)(op.bias + col);
                unsigned h0, l0, h1, l1;
                split2((acc[mf][ng][0] + bb.x) * op.oscale,
                       (acc[mf][ng][1] + bb.y) * op.oscale, h0, l0);
                split2((acc[mf][ng][2] + bb.x) * op.oscale,
                       (acc[mf][ng][3] + bb.y) * op.oscale, h1, l1);
                const size_t i0 = (size_t)row * (N / 2) + col / 2;
                const size_t i1 = (size_t)(row + 8) * (N / 2) + col / 2;
                op.Hout[i0] = h0; op.Lout[i0] = l0;
                op.Hout[i1] = h1; op.Lout[i1] = l1;
            }
        }
    } else {
#pragma unroll
        for (int mf = 0; mf < 2; mf++) {
#pragma unroll
            for (int ng = 0; ng < 8; ng++) {
                const int row = r0 + mf * 16;
                const int col = c0 + ng * 8;
                const float2 bb = *(const float2*)(op.bias + col);
                float2 v0, v1;
                v0.x = acc[mf][ng][0] + bb.x;
                v0.y = acc[mf][ng][1] + bb.y;
                v1.x = acc[mf][ng][2] + bb.x;
                v1.y = acc[mf][ng][3] + bb.y;
                *(float2*)(op.C + (size_t)row * N + col) = v0;
                *(float2*)(op.C + (size_t)(row + 8) * N + col) = v1;
            }
        }
    }
}

// Fused Q/K/V projection: gridDim.z = 3 selects operand set.
__global__ __launch_bounds__(256, 2)
void gemm_qkv(const unsigned short* qh, const unsigned short* ql,
              const unsigned short* kh, const unsigned short* kl,
              const unsigned short* vh, const unsigned short* vl,
              const unsigned short* Wqh, const unsigned short* Wql,
              const unsigned short* Wkh, const unsigned short* Wkl,
              const unsigned short* Wvh, const unsigned short* Wvl,
              const float* bq, const float* bk, const float* bv,
              unsigned* Qh, unsigned* Ql, unsigned* Kh, unsigned* Kl,
              unsigned* Vh, unsigned* Vl, int M, int N, int K) {
    extern __shared__ char smem_raw[];
    const unsigned sbase = smem_u32(smem_raw);
    const int z = blockIdx.z;
    GemmOps op;
    if (z == 0) {
        op = {qh, ql, Wqh, Wql, bq, nullptr, Qh, Ql, QSC};
    } else if (z == 1) {
        op = {kh, kl, Wkh, Wkl, bk, nullptr, Kh, Kl, 1.0f};
    } else {
        op = {vh, vl, Wvh, Wvl, bv, nullptr, Vh, Vl, 1.0f};
    }
    gemm_body(op, blockIdx.y * 128, blockIdx.x * 128, sbase, M, N, K);
}

// Out-projection: fp32 output.
__global__ __launch_bounds__(256, 2)
void gemm_out(const unsigned short* Ah, const unsigned short* Al,
              const unsigned short* Wh, const unsigned short* Wl,
              const float* bias, float* C, int M, int N, int K) {
    extern __shared__ char smem_raw[];
    const unsigned sbase = smem_u32(smem_raw);
    GemmOps op = {Ah, Al, Wh, Wl, bias, C, nullptr, nullptr, 1.0f};
    gemm_body(op, blockIdx.y * 128, blockIdx.x * 128, sbase, M, N, K);
}

// ============================================================================
// Flash attention on pre-split bf16 (causal, base-2 softmax). (unchanged R6)
// ============================================================================
#define FA_DSMEM 131072
#define KV_STG 32768
#define SM_Q 98304

__global__ __launch_bounds__(256, 1)
void flash_attn_bf16(const unsigned short* __restrict__ Qh,
                     const unsigned short* __restrict__ Ql,
                     const unsigned short* __restrict__ Kh,
                     const unsigned short* __restrict__ Kl,
                     const unsigned short* __restrict__ Vh,
                     const unsigned short* __restrict__ Vl,
                     unsigned short* __restrict__ Oh,
                     unsigned short* __restrict__ Ol) {
    extern __shared__ char sm[];
    const unsigned sb = smem_u32(sm);
    const int tid = threadIdx.x;
    const int lane = tid & 31;
    const int wid = tid >> 5;

    const int idx = blockIdx.x;
    const int bx = 15 - (idx >> 5);
    const int rem = idx & 31;
    const int h = rem & 15;
    const int b = rem >> 4;
    const int bq = bx * 128;
    const int wm = wid * 16;
    const int ntiles = 2 * bx + 2;

    auto stage_kv = [&](int t) {
        const unsigned stb = sb + (unsigned)(t % 3) * KV_STG;
        const int j0 = t * 64;
        const size_t rb = ((size_t)(b * S_ + j0)) * E_ + h * 64;
#pragma unroll
        for (int i = 0; i < 2; i++) {
            const int g = tid + i * 256;
            const int row = g >> 3, seg = g & 7;
            const unsigned sw = SW128((unsigned)(row * 128 + seg * 16));
            const size_t src = rb + (size_t)row * E_ + seg * 8;
            CP16(stb + sw,          Kh + src);
            CP16(stb + 8192 + sw,   Kl + src);
            CP16(stb + 16384 + sw,  Vh + src);
            CP16(stb + 24576 + sw,  Vl + src);
        }
        CP_COMMIT();
    };

    {
        const size_t rb = ((size_t)(b * S_ + bq)) * E_ + h * 64;
#pragma unroll
        for (int i = 0; i < 4; i++) {
            const int g = tid + i * 256;
            const int row = g >> 3, seg = g & 7;
            const unsigned sw = SW128((unsigned)(row * 128 + seg * 16));
            const size_t src = rb + (size_t)row * E_ + seg * 8;
            CP16(sb + SM_Q + sw,         Qh + src);
            CP16(sb + SM_Q + 16384 + sw, Ql + src);
        }
    }
    stage_kv(0);
    stage_kv(1);

    float accO[8][4];
#pragma unroll
    for (int f = 0; f < 8; f++)
#pragma unroll
        for (int j = 0; j < 4; j++) accO[f][j] = 0.0f;
    float m0 = -1e30f, m1 = -1e30f, l0 = 0.0f, l1 = 0.0f;

    unsigned aQh[4][4], aQl[4][4];

    const unsigned bLoc = ((unsigned)lane & 7) + (((unsigned)lane & 16) >> 1);
    const unsigned bHalf = (((unsigned)lane >> 3) & 1) * 16;
    const unsigned vRowBase = ((unsigned)lane & 7) + ((unsigned)lane & 8);
    const unsigned vHalf = (((unsigned)lane >> 4) & 1) * 16;

    for (int t = 0; t < ntiles; t++) {
        if (t + 1 < ntiles) { CP_WAIT(1); } else { CP_WAIT(0); }
        __syncthreads();
        if (t + 2 < ntiles) stage_kv(t + 2);

        if (t == 0) {
            const unsigned qrow = (unsigned)((wm + (lane & 15)) * 128);
            const unsigned qhalf = ((unsigned)lane >> 4) * 16;
#pragma unroll
            for (int kc = 0; kc < 4; kc++) {
                const unsigned sw = SW128(qrow + (unsigned)(kc * 32) + qhalf);
                ldsm4(aQh[kc], sb + SM_Q + sw);
                ldsm4(aQl[kc], sb + SM_Q + 16384 + sw);
            }
        }

        const unsigned stb = sb + (unsigned)(t % 3) * KV_STG;
        const int j0 = t * 64;

        float accS[8][4];
#pragma unroll
        for (int f = 0; f < 8; f++)
#pragma unroll
            for (int j = 0; j < 4; j++) accS[f][j] = 0.0f;

#pragma unroll
        for (int kc = 0; kc < 4; kc++) {
#pragma unroll
            for (int ng = 0; ng < 4; ng++) {
                const unsigned row = (unsigned)(ng * 16) + bLoc;
                const unsigned sw = SW128(row * 128 + (unsigned)(kc * 32) + bHalf);
                unsigned kh[4], kl[4];
                ldsm4(kh, stb + sw);
                ldsm4(kl, stb + 8192 + sw);
                mma16816(accS[2 * ng],     aQh[kc], kh[0], kh[1]);
                mma16816(accS[2 * ng + 1], aQh[kc], kh[2], kh[3]);
                mma16816(accS[2 * ng],     aQl[kc], kh[0], kh[1]);
                mma16816(accS[2 * ng + 1], aQl[kc], kh[2], kh[3]);
                mma16816(accS[2 * ng],     aQh[kc], kl[0], kl[1]);
                mma16816(accS[2 * ng + 1], aQh[kc], kl[2], kl[3]);
            }
        }

        const int row0 = bq + wm + (lane >> 2);
        const int row1 = row0 + 8;

        if (j0 + 63 > bq + wm) {
#pragma unroll
            for (int f = 0; f < 8; f++) {
                const int c0 = j0 + f * 8 + (lane & 3) * 2;
                if (c0 > row0)     accS[f][0] = -1e30f;
                if (c0 + 1 > row0) accS[f][1] = -1e30f;
                if (c0 > row1)     accS[f][2] = -1e30f;
                if (c0 + 1 > row1) accS[f][3] = -1e30f;
            }
        }

        float rm0 = -1e30f, rm1 = -1e30f;
#pragma unroll
        for (int f = 0; f < 8; f++) {
            rm0 = fmaxf(rm0, fmaxf(accS[f][0], accS[f][1]));
            rm1 = fmaxf(rm1, fmaxf(accS[f][2], accS[f][3]));
        }
        rm0 = fmaxf(rm0, __shfl_xor_sync(0xFFFFFFFF, rm0, 1));
        rm0 = fmaxf(rm0, __shfl_xor_sync(0xFFFFFFFF, rm0, 2));
        rm1 = fmaxf(rm1, __shfl_xor_sync(0xFFFFFFFF, rm1, 1));
        rm1 = fmaxf(rm1, __shfl_xor_sync(0xFFFFFFFF, rm1, 2));
        const float mn0 = fmaxf(m0, rm0);
        const float mn1 = fmaxf(m1, rm1);
        const float sc0 = exp2p(m0 - mn0);
        const float sc1 = exp2p(m1 - mn1);
        m0 = mn0; m1 = mn1;
        l0 *= sc0; l1 *= sc1;
#pragma unroll
        for (int f = 0; f < 8; f++) {
            accO[f][0] *= sc0; accO[f][1] *= sc0;
            accO[f][2] *= sc1; accO[f][3] *= sc1;
        }

        float sump0 = 0.0f, sump1 = 0.0f;
#pragma unroll
        for (int kc = 0; kc < 4; kc++) {
            const int f0 = 2 * kc, f1 = 2 * kc + 1;
            const float p00 = exp2p(accS[f0][0] - m0);
            const float p01 = exp2p(accS[f0][1] - m0);
            const float p02 = exp2p(accS[f0][2] - m1);
            const float p03 = exp2p(accS[f0][3] - m1);
            const float p10 = exp2p(accS[f1][0] - m0);
            const float p11 = exp2p(accS[f1][1] - m0);
            const float p12 = exp2p(accS[f1][2] - m1);
            const float p13 = exp2p(accS[f1][3] - m1);
            sump0 += (p00 + p01) + (p10 + p11);
            sump1 += (p02 + p03) + (p12 + p13);
            unsigned ph[4], pl[4];
            split2(p00, p01, ph[0], pl[0]);
            split2(p02, p03, ph[1], pl[1]);
            split2(p10, p11, ph[2], pl[2]);
            split2(p12, p13, ph[3], pl[3]);

            const unsigned vrow = (unsigned)(kc * 16) + vRowBase;
#pragma unroll
            for (int nd = 0; nd < 4; nd++) {
                const unsigned sw = SW128(vrow * 128 + (unsigned)(nd * 32) + vHalf);
                unsigned vh[4], vl[4];
                ldsm4t(vh, stb + 16384 + sw);
                ldsm4t(vl, stb + 24576 + sw);
                mma16816(accO[2 * nd],     ph, vh[0], vh[1]);
                mma16816(accO[2 * nd + 1], ph, vh[2], vh[3]);
                mma16816(accO[2 * nd],     pl, vh[0], vh[1]);
                mma16816(accO[2 * nd + 1], pl, vh[2], vh[3]);
                mma16816(accO[2 * nd],     ph, vl[0], vl[1]);
                mma16816(accO[2 * nd + 1], ph, vl[2], vl[3]);
            }
        }
        l0 += sump0;
        l1 += sump1;
    }

    l0 += __shfl_xor_sync(0xFFFFFFFF, l0, 1);
    l0 += __shfl_xor_sync(0xFFFFFFFF, l0, 2);
    l1 += __shfl_xor_sync(0xFFFFFFFF, l1, 1);
    l1 += __shfl_xor_sync(0xFFFFFFFF, l1, 2);
    const float inv0 = 1.0f / l0;
    const float inv1 = 1.0f / l1;

    const int row0 = bq + wm + (lane >> 2);
    unsigned* OhU = (unsigned*)Oh;
    unsigned* OlU = (unsigned*)Ol;
#pragma unroll
    for (int f = 0; f < 8; f++) {
        const int col = f * 8 + (lane & 3) * 2;
        const size_t i0 = ((size_t)(b * S_ + row0)) * (E_ / 2) + h * 32 + col / 2;
        const size_t i1 = ((size_t)(b * S_ + row0 + 8)) * (E_ / 2) + h * 32 + col / 2;
        unsigned h0, l0u, h1, l1u;
        split2(accO[f][0] * inv0, accO[f][1] * inv0, h0, l0u);
        split2(accO[f][2] * inv1, accO[f][3] * inv1, h1, l1u);
        OhU[i0] = h0; OlU[i0] = l0u;
        OhU[i1] = h1; OlU[i1] = l1u;
    }
}

// ============================================================================
// Launch
// ============================================================================
extern "C" void kernel_launch(void* const* d_in, const int* in_sizes, int n_in,
                              void* d_out, int out_size) {
    (void)in_sizes; (void)n_in; (void)out_size;

    const float* q  = (const float*)d_in[0];
    const float* k  = (const float*)d_in[1];
    const float* v  = (const float*)d_in[2];
    const float* Wq = (const float*)d_in[4];
    const float* bq = (const float*)d_in[5];
    const float* Wk = (const float*)d_in[6];
    const float* bk = (const float*)d_in[7];
    const float* Wv = (const float*)d_in[8];
    const float* bv = (const float*)d_in[9];
    const float* Wo = (const float*)d_in[10];
    const float* bo = (const float*)d_in[11];
    float* out = (float*)d_out;

    unsigned short *qh, *ql, *kh, *kl, *vh, *vl;
    unsigned short *Wqh, *Wql, *Wkh, *Wkl, *Wvh, *Wvl, *Woh, *Wol;
    unsigned short *Qh, *Ql, *Kh, *Kl, *Vh, *Vl, *Ch, *Cl;
    cudaGetSymbolAddress((void**)&qh, g_qh);   cudaGetSymbolAddress((void**)&ql, g_ql);
    cudaGetSymbolAddress((void**)&kh, g_kh);   cudaGetSymbolAddress((void**)&kl, g_kl);
    cudaGetSymbolAddress((void**)&vh, g_vh);   cudaGetSymbolAddress((void**)&vl, g_vl);
    cudaGetSymbolAddress((void**)&Wqh, g_Wqh); cudaGetSymbolAddress((void**)&Wql, g_Wql);
    cudaGetSymbolAddress((void**)&Wkh, g_Wkh); cudaGetSymbolAddress((void**)&Wkl, g_Wkl);
    cudaGetSymbolAddress((void**)&Wvh, g_Wvh); cudaGetSymbolAddress((void**)&Wvl, g_Wvl);
    cudaGetSymbolAddress((void**)&Woh, g_Woh); cudaGetSymbolAddress((void**)&Wol, g_Wol);
    cudaGetSymbolAddress((void**)&Qh, g_Qh);   cudaGetSymbolAddress((void**)&Ql, g_Ql);
    cudaGetSymbolAddress((void**)&Kh, g_Kh);   cudaGetSymbolAddress((void**)&Kl, g_Kl);
    cudaGetSymbolAddress((void**)&Vh, g_Vh);   cudaGetSymbolAddress((void**)&Vl, g_Vl);
    cudaGetSymbolAddress((void**)&Ch, g_Ch);   cudaGetSymbolAddress((void**)&Cl, g_Cl);

    cudaFuncSetAttribute(gemm_qkv, cudaFuncAttributeMaxDynamicSharedMemorySize,
                         GM_DSMEM);
    cudaFuncSetAttribute(gemm_out, cudaFuncAttributeMaxDynamicSharedMemorySize,
                         GM_DSMEM);
    cudaFuncSetAttribute(flash_attn_bf16, cudaFuncAttributeMaxDynamicSharedMemorySize,
                         FA_DSMEM);

    const int M = B_ * S_;   // 4096
    const int N = E_;        // 1024
    const int K = E_;        // 1024

    // ---- pre-split inputs + weights ----
    const int mn4 = ME_ / 4, wn4 = WE_ / 4;
    presplit<<<mn4 / 256, 256>>>(q, (unsigned*)qh, (unsigned*)ql, mn4);
    presplit<<<mn4 / 256, 256>>>(k, (unsigned*)kh, (unsigned*)kl, mn4);
    presplit<<<mn4 / 256, 256>>>(v, (unsigned*)vh, (unsigned*)vl, mn4);
    presplit<<<wn4 / 256, 256>>>(Wq, (unsigned*)Wqh, (unsigned*)Wql, wn4);
    presplit<<<wn4 / 256, 256>>>(Wk, (unsigned*)Wkh, (unsigned*)Wkl, wn4);
    presplit<<<wn4 / 256, 256>>>(Wv, (unsigned*)Wvh, (unsigned*)Wvl, wn4);
    presplit<<<wn4 / 256, 256>>>(Wo, (unsigned*)Woh, (unsigned*)Wol, wn4);

    // ---- fused QKV projections ----
    dim3 qgrid(N / 128, M / 128, 3);   // (8, 32, 3)
    gemm_qkv<<<qgrid, 256, GM_DSMEM>>>(qh, ql, kh, kl, vh, vl,
                                       Wqh, Wql, Wkh, Wkl, Wvh, Wvl,
                                       bq, bk, bv,
                                       (unsigned*)Qh, (unsigned*)Ql,
                                       (unsigned*)Kh, (unsigned*)Kl,
                                       (unsigned*)Vh, (unsigned*)Vl, M, N, K);

    flash_attn_bf16<<<512, 256, FA_DSMEM>>>(Qh, Ql, Kh, Kl, Vh, Vl, Ch, Cl);

    dim3 ogrid(N / 128, M / 128);
    gemm_out<<<ogrid, 256, GM_DSMEM>>>(Ch, Cl, Woh, Wol, bo, out, M, N, K);
}

// round 9
// speedup vs baseline: 4.7291x; 1.0496x over previous
#include <cuda_runtime.h>
#include <cuda_bf16.h>
#include <math.h>

#define B_ 2
#define S_ 2048
#define E_ 1024
#define H_ 16
#define D_ 64
#define ME_ (B_ * S_ * E_)   // 4M elements
#define WE_ (E_ * E_)        // 1M elements

// Scratch (allocation-free rule: __device__ globals)
__device__ unsigned short g_qh[ME_], g_ql[ME_];
__device__ unsigned short g_kh[ME_], g_kl[ME_];
__device__ unsigned short g_vh[ME_], g_vl[ME_];
__device__ unsigned short g_Wqh[WE_], g_Wql[WE_];
__device__ unsigned short g_Wkh[WE_], g_Wkl[WE_];
__device__ unsigned short g_Wvh[WE_], g_Wvl[WE_];
__device__ unsigned short g_Woh[WE_], g_Wol[WE_];
__device__ unsigned short g_Qh[ME_], g_Ql[ME_];
__device__ unsigned short g_Kh[ME_], g_Kl[ME_];
__device__ unsigned short g_Vh[ME_], g_Vl[ME_];
__device__ unsigned short g_Ch[ME_], g_Cl[ME_];

// ============================================================================
// Helpers
// ============================================================================
__device__ __forceinline__ unsigned smem_u32(const void* p) {
    unsigned a;
    asm("{ .reg .u64 t; cvta.to.shared.u64 t, %1; cvt.u32.u64 %0, t; }"
        : "=r"(a) : "l"(p));
    return a;
}

#define CP16(dst, src) \
    asm volatile("cp.async.cg.shared.global [%0], [%1], 16;" \
                 :: "r"((unsigned)(dst)), "l"(src) : "memory")
#define CP_COMMIT() asm volatile("cp.async.commit_group;" ::: "memory")
#define CP_WAIT(n)  asm volatile("cp.async.wait_group %0;" :: "n"(n) : "memory")

__device__ __forceinline__ void ldsm4(unsigned* r, unsigned addr) {
    asm volatile("ldmatrix.sync.aligned.m8n8.x4.shared.b16 {%0,%1,%2,%3}, [%4];"
                 : "=r"(r[0]), "=r"(r[1]), "=r"(r[2]), "=r"(r[3]) : "r"(addr));
}
__device__ __forceinline__ void ldsm4t(unsigned* r, unsigned addr) {
    asm volatile("ldmatrix.sync.aligned.m8n8.x4.trans.shared.b16 {%0,%1,%2,%3}, [%4];"
                 : "=r"(r[0]), "=r"(r[1]), "=r"(r[2]), "=r"(r[3]) : "r"(addr));
}

__device__ __forceinline__ void mma16816(float* d, const unsigned* a,
                                         unsigned b0, unsigned b1) {
    asm volatile(
        "mma.sync.aligned.m16n8k16.row.col.f32.bf16.bf16.f32 "
        "{%0,%1,%2,%3}, {%4,%5,%6,%7}, {%8,%9}, {%0,%1,%2,%3};"
        : "+f"(d[0]), "+f"(d[1]), "+f"(d[2]), "+f"(d[3])
        : "r"(a[0]), "r"(a[1]), "r"(a[2]), "r"(a[3]), "r"(b0), "r"(b1));
}

__device__ __forceinline__ unsigned pack_bf2(float flo, float fhi) {
    unsigned r;
    asm("cvt.rn.bf16x2.f32 %0, %1, %2;" : "=r"(r) : "f"(fhi), "f"(flo));
    return r;
}
__device__ __forceinline__ void split2(float x0, float x1, unsigned& hi, unsigned& lo) {
    hi = pack_bf2(x0, x1);
    float h0 = __uint_as_float(hi << 16);
    float h1 = __uint_as_float(hi & 0xFFFF0000u);
    lo = pack_bf2(x0 - h0, x1 - h1);
}

// fast 2^t on the fma pipe (t <= 0), err ~2e-6
__device__ __forceinline__ float exp2p(float t) {
    t = fmaxf(t, -126.0f);
    float z = t + 12582912.0f;
    float r = t - (z - 12582912.0f);
    float p = 0.0013333558f;
    p = fmaf(p, r, 0.0096181291f);
    p = fmaf(p, r, 0.0555041087f);
    p = fmaf(p, r, 0.2402265069f);
    p = fmaf(p, r, 0.6931471806f);
    p = fmaf(p, r, 1.0f);
    unsigned eb = (__float_as_uint(z) << 23) + 0x3F800000u;
    return __uint_as_float(eb) * p;
}

#define SW128(o) ((o) ^ (((o) >> 3) & 0x70))
#define QSC 0.1803368801111244f   // 0.125 * log2(e)

// ============================================================================
// Pre-split: fp32 -> bf16 hi/lo (fused: 3 inputs / 4 weights per launch)
// ============================================================================
__global__ __launch_bounds__(256)
void presplit3(const float* __restrict__ X0, const float* __restrict__ X1,
               const float* __restrict__ X2,
               unsigned* H0, unsigned* L0, unsigned* H1, unsigned* L1,
               unsigned* H2, unsigned* L2, int n4) {
    const int i = blockIdx.x * 256 + threadIdx.x;
    if (i >= n4) return;
    const float* X = (blockIdx.y == 0) ? X0 : (blockIdx.y == 1) ? X1 : X2;
    unsigned* Hx = (blockIdx.y == 0) ? H0 : (blockIdx.y == 1) ? H1 : H2;
    unsigned* Lx = (blockIdx.y == 0) ? L0 : (blockIdx.y == 1) ? L1 : L2;
    const float4 x = ((const float4*)X)[i];
    unsigned h0, l0, h1, l1;
    split2(x.x, x.y, h0, l0);
    split2(x.z, x.w, h1, l1);
    ((uint2*)Hx)[i] = make_uint2(h0, h1);
    ((uint2*)Lx)[i] = make_uint2(l0, l1);
}

__global__ __launch_bounds__(256)
void presplit4(const float* __restrict__ X0, const float* __restrict__ X1,
               const float* __restrict__ X2, const float* __restrict__ X3,
               unsigned* H0, unsigned* L0, unsigned* H1, unsigned* L1,
               unsigned* H2, unsigned* L2, unsigned* H3, unsigned* L3, int n4) {
    const int i = blockIdx.x * 256 + threadIdx.x;
    if (i >= n4) return;
    const float* X = (blockIdx.y == 0) ? X0 : (blockIdx.y == 1) ? X1
                   : (blockIdx.y == 2) ? X2 : X3;
    unsigned* Hx = (blockIdx.y == 0) ? H0 : (blockIdx.y == 1) ? H1
                 : (blockIdx.y == 2) ? H2 : H3;
    unsigned* Lx = (blockIdx.y == 0) ? L0 : (blockIdx.y == 1) ? L1
                 : (blockIdx.y == 2) ? L2 : L3;
    const float4 x = ((const float4*)X)[i];
    unsigned h0, l0, h1, l1;
    split2(x.x, x.y, h0, l0);
    split2(x.z, x.w, h1, l1);
    ((uint2*)Hx)[i] = make_uint2(h0, h1);
    ((uint2*)Lx)[i] = make_uint2(l0, l1);
}

// ============================================================================
// GEMM core (NT) on pre-split bf16, 2-stage ring, occupancy 2. (unchanged R7)
// ============================================================================
#define PIECE 8192
#define GSTG 32768
#define GM_DSMEM (2 * GSTG)

struct GemmOps {
    const unsigned short *Ah, *Al, *Wh, *Wl;
    const float* bias;
    float* C;
    unsigned *Hout, *Lout;
    float oscale;
};

__device__ __forceinline__ void gemm_body(const GemmOps& op, int bm, int bn,
                                          unsigned sbase, int M, int N, int K) {
    const int tid = threadIdx.x;
    const int lane = tid & 31;
    const int wid = tid >> 5;

    auto stage = [&](int c) {
        const unsigned stb = sbase + (unsigned)(c & 1) * GSTG;
#pragma unroll
        for (int i = 0; i < 2; i++) {
            const int g = tid + i * 256;
            const int row = g >> 2, c16 = g & 3;
            const unsigned dst = (unsigned)(row * 64) +
                                 ((((unsigned)c16) ^ (((unsigned)row >> 1) & 3)) << 4);
            const size_t sA = (size_t)(bm + row) * K + c * 32 + c16 * 8;
            const size_t sW = (size_t)(bn + row) * K + c * 32 + c16 * 8;
            CP16(stb + dst,             op.Ah + sA);
            CP16(stb + PIECE + dst,     op.Al + sA);
            CP16(stb + 2 * PIECE + dst, op.Wh + sW);
            CP16(stb + 3 * PIECE + dst, op.Wl + sW);
        }
        CP_COMMIT();
    };

    const int wm = (wid & 3) * 32;
    const int wn = (wid >> 2) * 64;
    const unsigned aRow = (unsigned)((wm + (lane & 15)) * 64);
    const unsigned aG = (((unsigned)lane & 15) >> 1) & 3;
    const unsigned aHalf = (unsigned)lane >> 4;
    const unsigned bLocal = ((unsigned)lane & 7) + (((unsigned)lane & 16) >> 1);
    const unsigned bRow = (unsigned)((wn + (int)bLocal) * 64);
    const unsigned bG = (bLocal >> 1) & 3;
    const unsigned bHalf = ((unsigned)lane >> 3) & 1;

    float acc[2][8][4];
#pragma unroll
    for (int i = 0; i < 2; i++)
#pragma unroll
        for (int j = 0; j < 8; j++)
#pragma unroll
            for (int t = 0; t < 4; t++) acc[i][j][t] = 0.0f;

    auto compute = [&](unsigned stg) {
#pragma unroll
        for (int ks = 0; ks < 2; ks++) {
            unsigned ah0[4], ah1[4], al0[4], al1[4];
            const unsigned aoffs = (((unsigned)(2 * ks) + aHalf) ^ aG) << 4;
            ldsm4(ah0, stg + aRow + aoffs);
            ldsm4(ah1, stg + aRow + 1024 + aoffs);
            ldsm4(al0, stg + PIECE + aRow + aoffs);
            ldsm4(al1, stg + PIECE + aRow + 1024 + aoffs);
            const unsigned boffs = (((unsigned)(2 * ks) + bHalf) ^ bG) << 4;
#pragma unroll
            for (int ng = 0; ng < 4; ng++) {
                unsigned bh[4], bl[4];
                ldsm4(bh, stg + 2 * PIECE + bRow + ng * 1024 + boffs);
                ldsm4(bl, stg + 3 * PIECE + bRow + ng * 1024 + boffs);
                mma16816(acc[0][2 * ng],     ah0, bh[0], bh[1]);
                mma16816(acc[0][2 * ng + 1], ah0, bh[2], bh[3]);
                mma16816(acc[1][2 * ng],     ah1, bh[0], bh[1]);
                mma16816(acc[1][2 * ng + 1], ah1, bh[2], bh[3]);
                mma16816(acc[0][2 * ng],     ah0, bl[0], bl[1]);
                mma16816(acc[0][2 * ng + 1], ah0, bl[2], bl[3]);
                mma16816(acc[1][2 * ng],     ah1, bl[0], bl[1]);
                mma16816(acc[1][2 * ng + 1], ah1, bl[2], bl[3]);
                mma16816(acc[0][2 * ng],     al0, bh[0], bh[1]);
                mma16816(acc[0][2 * ng + 1], al0, bh[2], bh[3]);
                mma16816(acc[1][2 * ng],     al1, bh[0], bh[1]);
                mma16816(acc[1][2 * ng + 1], al1, bh[2], bh[3]);
            }
        }
    };

    const int nchunk = K / 32;
    stage(0);
    stage(1);
    for (int c = 0; c < nchunk; c++) {
        if (c + 1 < nchunk) { CP_WAIT(1); } else { CP_WAIT(0); }
        __syncthreads();
        compute(sbase + (unsigned)(c & 1) * GSTG);
        __syncthreads();
        if (c + 2 < nchunk) stage(c + 2);
    }

    const int r0 = bm + wm + (lane >> 2);
    const int c0 = bn + wn + (lane & 3) * 2;
    if (op.Hout) {
#pragma unroll
        for (int mf = 0; mf < 2; mf++) {
#pragma unroll
            for (int ng = 0; ng < 8; ng++) {
                const int row = r0 + mf * 16;
                const int col = c0 + ng * 8;
                const float2 bb = *(const float2*)(op.bias + col);
                unsigned h0, l0, h1, l1;
                split2((acc[mf][ng][0] + bb.x) * op.oscale,
                       (acc[mf][ng][1] + bb.y) * op.oscale, h0, l0);
                split2((acc[mf][ng][2] + bb.x) * op.oscale,
                       (acc[mf][ng][3] + bb.y) * op.oscale, h1, l1);
                const size_t i0 = (size_t)row * (N / 2) + col / 2;
                const size_t i1 = (size_t)(row + 8) * (N / 2) + col / 2;
                op.Hout[i0] = h0; op.Lout[i0] = l0;
                op.Hout[i1] = h1; op.Lout[i1] = l1;
            }
        }
    } else {
#pragma unroll
        for (int mf = 0; mf < 2; mf++) {
#pragma unroll
            for (int ng = 0; ng < 8; ng++) {
                const int row = r0 + mf * 16;
                const int col = c0 + ng * 8;
                const float2 bb = *(const float2*)(op.bias + col);
                float2 v0, v1;
                v0.x = acc[mf][ng][0] + bb.x;
                v0.y = acc[mf][ng][1] + bb.y;
                v1.x = acc[mf][ng][2] + bb.x;
                v1.y = acc[mf][ng][3] + bb.y;
                *(float2*)(op.C + (size_t)row * N + col) = v0;
                *(float2*)(op.C + (size_t)(row + 8) * N + col) = v1;
            }
        }
    }
}

__global__ __launch_bounds__(256, 2)
void gemm_qkv(const unsigned short* qh, const unsigned short* ql,
              const unsigned short* kh, const unsigned short* kl,
              const unsigned short* vh, const unsigned short* vl,
              const unsigned short* Wqh, const unsigned short* Wql,
              const unsigned short* Wkh, const unsigned short* Wkl,
              const unsigned short* Wvh, const unsigned short* Wvl,
              const float* bq, const float* bk, const float* bv,
              unsigned* Qh, unsigned* Ql, unsigned* Kh, unsigned* Kl,
              unsigned* Vh, unsigned* Vl, int M, int N, int K) {
    extern __shared__ char smem_raw[];
    const unsigned sbase = smem_u32(smem_raw);
    const int z = blockIdx.z;
    GemmOps op;
    if (z == 0) {
        op = {qh, ql, Wqh, Wql, bq, nullptr, Qh, Ql, QSC};
    } else if (z == 1) {
        op = {kh, kl, Wkh, Wkl, bk, nullptr, Kh, Kl, 1.0f};
    } else {
        op = {vh, vl, Wvh, Wvl, bv, nullptr, Vh, Vl, 1.0f};
    }
    gemm_body(op, blockIdx.y * 128, blockIdx.x * 128, sbase, M, N, K);
}

__global__ __launch_bounds__(256, 2)
void gemm_out(const unsigned short* Ah, const unsigned short* Al,
              const unsigned short* Wh, const unsigned short* Wl,
              const float* bias, float* C, int M, int N, int K) {
    extern __shared__ char smem_raw[];
    const unsigned sbase = smem_u32(smem_raw);
    GemmOps op = {Ah, Al, Wh, Wl, bias, C, nullptr, nullptr, 1.0f};
    gemm_body(op, blockIdx.y * 128, blockIdx.x * 128, sbase, M, N, K);
}

// ============================================================================
// Flash attention, occupancy-2 shape: 4 warps, 64 q-rows/CTA, 64-key tiles.
// smem per CTA: 2-stage KV ring (2x32KB) + Q hi/lo (16KB) = 80KB -> 2 CTAs/SM.
// grid = 1024 (LPT heavy-first), block = 128.
// ============================================================================
#define FA_DSMEM 81920
#define KV_STG 32768
#define SM_Q 65536

__global__ __launch_bounds__(128, 2)
void flash_attn_bf16(const unsigned short* __restrict__ Qh,
                     const unsigned short* __restrict__ Ql,
                     const unsigned short* __restrict__ Kh,
                     const unsigned short* __restrict__ Kl,
                     const unsigned short* __restrict__ Vh,
                     const unsigned short* __restrict__ Vl,
                     unsigned short* __restrict__ Oh,
                     unsigned short* __restrict__ Ol) {
    extern __shared__ char sm[];
    const unsigned sb = smem_u32(sm);
    const int tid = threadIdx.x;
    const int lane = tid & 31;
    const int wid = tid >> 5;          // 0..3

    // LPT remap: heavy (large bx) CTAs first
    const int idx = blockIdx.x;
    const int bx = 31 - (idx >> 5);
    const int rem = idx & 31;
    const int h = rem & 15;
    const int b = rem >> 4;
    const int bq = bx * 64;
    const int wm = wid * 16;
    const int ntiles = bx + 1;

    auto stage_kv = [&](int t) {
        const unsigned stb = sb + (unsigned)(t & 1) * KV_STG;
        const int j0 = t * 64;
        const size_t rb = ((size_t)(b * S_ + j0)) * E_ + h * 64;
#pragma unroll
        for (int i = 0; i < 4; i++) {
            const int g = tid + i * 128;          // 512 groups per piece
            const int row = g >> 3, seg = g & 7;
            const unsigned sw = SW128((unsigned)(row * 128 + seg * 16));
            const size_t src = rb + (size_t)row * E_ + seg * 8;
            CP16(stb + sw,          Kh + src);
            CP16(stb + 8192 + sw,   Kl + src);
            CP16(stb + 16384 + sw,  Vh + src);
            CP16(stb + 24576 + sw,  Vl + src);
        }
        CP_COMMIT();
    };

    // ---- stage Q (64 rows, hi/lo) ----
    {
        const size_t rb = ((size_t)(b * S_ + bq)) * E_ + h * 64;
#pragma unroll
        for (int i = 0; i < 4; i++) {
            const int g = tid + i * 128;
            const int row = g >> 3, seg = g & 7;
            const unsigned sw = SW128((unsigned)(row * 128 + seg * 16));
            const size_t src = rb + (size_t)row * E_ + seg * 8;
            CP16(sb + SM_Q + sw,        Qh + src);
            CP16(sb + SM_Q + 8192 + sw, Ql + src);
        }
    }
    stage_kv(0);   // Q rides in group 0 with KV tile 0
    stage_kv(1);

    float accO[8][4];
#pragma unroll
    for (int f = 0; f < 8; f++)
#pragma unroll
        for (int j = 0; j < 4; j++) accO[f][j] = 0.0f;
    float m0 = -1e30f, m1 = -1e30f, l0 = 0.0f, l1 = 0.0f;

    unsigned aQh[4][4], aQl[4][4];

    const unsigned bLoc = ((unsigned)lane & 7) + (((unsigned)lane & 16) >> 1);
    const unsigned bHalf = (((unsigned)lane >> 3) & 1) * 16;
    const unsigned vRowBase = ((unsigned)lane & 7) + ((unsigned)lane & 8);
    const unsigned vHalf = (((unsigned)lane >> 4) & 1) * 16;

    for (int t = 0; t < ntiles; t++) {
        if (t + 1 < ntiles) { CP_WAIT(1); } else { CP_WAIT(0); }
        __syncthreads();

        if (t == 0) {
            const unsigned qrow = (unsigned)((wm + (lane & 15)) * 128);
            const unsigned qhalf = ((unsigned)lane >> 4) * 16;
#pragma unroll
            for (int kc = 0; kc < 4; kc++) {
                const unsigned sw = SW128(qrow + (unsigned)(kc * 32) + qhalf);
                ldsm4(aQh[kc], sb + SM_Q + sw);
                ldsm4(aQl[kc], sb + SM_Q + 8192 + sw);
            }
        }

        const unsigned stb = sb + (unsigned)(t & 1) * KV_STG;
        const int j0 = t * 64;

        // ---- S = Q K^T (3-term split) ----
        float accS[8][4];
#pragma unroll
        for (int f = 0; f < 8; f++)
#pragma unroll
            for (int j = 0; j < 4; j++) accS[f][j] = 0.0f;

#pragma unroll
        for (int kc = 0; kc < 4; kc++) {
#pragma unroll
            for (int ng = 0; ng < 4; ng++) {
                const unsigned row = (unsigned)(ng * 16) + bLoc;
                const unsigned sw = SW128(row * 128 + (unsigned)(kc * 32) + bHalf);
                unsigned kh[4], kl[4];
                ldsm4(kh, stb + sw);
                ldsm4(kl, stb + 8192 + sw);
                mma16816(accS[2 * ng],     aQh[kc], kh[0], kh[1]);
                mma16816(accS[2 * ng + 1], aQh[kc], kh[2], kh[3]);
                mma16816(accS[2 * ng],     aQl[kc], kh[0], kh[1]);
                mma16816(accS[2 * ng + 1], aQl[kc], kh[2], kh[3]);
                mma16816(accS[2 * ng],     aQh[kc], kl[0], kl[1]);
                mma16816(accS[2 * ng + 1], aQh[kc], kl[2], kl[3]);
            }
        }

        const int row0 = bq + wm + (lane >> 2);
        const int row1 = row0 + 8;

        // ---- causal mask (last tile only for most warps) ----
        if (j0 + 63 > bq + wm) {
#pragma unroll
            for (int f = 0; f < 8; f++) {
                const int c0 = j0 + f * 8 + (lane & 3) * 2;
                if (c0 > row0)     accS[f][0] = -1e30f;
                if (c0 + 1 > row0) accS[f][1] = -1e30f;
                if (c0 > row1)     accS[f][2] = -1e30f;
                if (c0 + 1 > row1) accS[f][3] = -1e30f;
            }
        }

        // ---- online softmax ----
        float rm0 = -1e30f, rm1 = -1e30f;
#pragma unroll
        for (int f = 0; f < 8; f++) {
            rm0 = fmaxf(rm0, fmaxf(accS[f][0], accS[f][1]));
            rm1 = fmaxf(rm1, fmaxf(accS[f][2], accS[f][3]));
        }
        rm0 = fmaxf(rm0, __shfl_xor_sync(0xFFFFFFFF, rm0, 1));
        rm0 = fmaxf(rm0, __shfl_xor_sync(0xFFFFFFFF, rm0, 2));
        rm1 = fmaxf(rm1, __shfl_xor_sync(0xFFFFFFFF, rm1, 1));
        rm1 = fmaxf(rm1, __shfl_xor_sync(0xFFFFFFFF, rm1, 2));
        const float mn0 = fmaxf(m0, rm0);
        const float mn1 = fmaxf(m1, rm1);
        const float sc0 = exp2p(m0 - mn0);
        const float sc1 = exp2p(m1 - mn1);
        m0 = mn0; m1 = mn1;
        l0 *= sc0; l1 *= sc1;
#pragma unroll
        for (int f = 0; f < 8; f++) {
            accO[f][0] *= sc0; accO[f][1] *= sc0;
            accO[f][2] *= sc1; accO[f][3] *= sc1;
        }

        // ---- P = exp2(S - m); O += P V (3-term split) ----
        float sump0 = 0.0f, sump1 = 0.0f;
#pragma unroll
        for (int kc = 0; kc < 4; kc++) {
            const int f0 = 2 * kc, f1 = 2 * kc + 1;
            const float p00 = exp2p(accS[f0][0] - m0);
            const float p01 = exp2p(accS[f0][1] - m0);
            const float p02 = exp2p(accS[f0][2] - m1);
            const float p03 = exp2p(accS[f0][3] - m1);
            const float p10 = exp2p(accS[f1][0] - m0);
            const float p11 = exp2p(accS[f1][1] - m0);
            const float p12 = exp2p(accS[f1][2] - m1);
            const float p13 = exp2p(accS[f1][3] - m1);
            sump0 += (p00 + p01) + (p10 + p11);
            sump1 += (p02 + p03) + (p12 + p13);
            unsigned ph[4], pl[4];
            split2(p00, p01, ph[0], pl[0]);
            split2(p02, p03, ph[1], pl[1]);
            split2(p10, p11, ph[2], pl[2]);
            split2(p12, p13, ph[3], pl[3]);

            const unsigned vrow = (unsigned)(kc * 16) + vRowBase;
#pragma unroll
            for (int nd = 0; nd < 4; nd++) {
                const unsigned sw = SW128(vrow * 128 + (unsigned)(nd * 32) + vHalf);
                unsigned vh[4], vl[4];
                ldsm4t(vh, stb + 16384 + sw);
                ldsm4t(vl, stb + 24576 + sw);
                mma16816(accO[2 * nd],     ph, vh[0], vh[1]);
                mma16816(accO[2 * nd + 1], ph, vh[2], vh[3]);
                mma16816(accO[2 * nd],     pl, vh[0], vh[1]);
                mma16816(accO[2 * nd + 1], pl, vh[2], vh[3]);
                mma16816(accO[2 * nd],     ph, vl[0], vl[1]);
                mma16816(accO[2 * nd + 1], ph, vl[2], vl[3]);
            }
        }
        l0 += sump0;
        l1 += sump1;

        __syncthreads();                    // all warps done with buffer (t&1)
        if (t + 2 < ntiles) stage_kv(t + 2);
    }

    // ---- finalize: write pre-split O ----
    l0 += __shfl_xor_sync(0xFFFFFFFF, l0, 1);
    l0 += __shfl_xor_sync(0xFFFFFFFF, l0, 2);
    l1 += __shfl_xor_sync(0xFFFFFFFF, l1, 1);
    l1 += __shfl_xor_sync(0xFFFFFFFF, l1, 2);
    const float inv0 = 1.0f / l0;
    const float inv1 = 1.0f / l1;

    const int row0 = bq + wm + (lane >> 2);
    unsigned* OhU = (unsigned*)Oh;
    unsigned* OlU = (unsigned*)Ol;
#pragma unroll
    for (int f = 0; f < 8; f++) {
        const int col = f * 8 + (lane & 3) * 2;
        const size_t i0 = ((size_t)(b * S_ + row0)) * (E_ / 2) + h * 32 + col / 2;
        const size_t i1 = ((size_t)(b * S_ + row0 + 8)) * (E_ / 2) + h * 32 + col / 2;
        unsigned h0, l0u, h1, l1u;
        split2(accO[f][0] * inv0, accO[f][1] * inv0, h0, l0u);
        split2(accO[f][2] * inv1, accO[f][3] * inv1, h1, l1u);
        OhU[i0] = h0; OlU[i0] = l0u;
        OhU[i1] = h1; OlU[i1] = l1u;
    }
}

// ============================================================================
// Launch
// ============================================================================
extern "C" void kernel_launch(void* const* d_in, const int* in_sizes, int n_in,
                              void* d_out, int out_size) {
    (void)in_sizes; (void)n_in; (void)out_size;

    const float* q  = (const float*)d_in[0];
    const float* k  = (const float*)d_in[1];
    const float* v  = (const float*)d_in[2];
    const float* Wq = (const float*)d_in[4];
    const float* bq = (const float*)d_in[5];
    const float* Wk = (const float*)d_in[6];
    const float* bk = (const float*)d_in[7];
    const float* Wv = (const float*)d_in[8];
    const float* bv = (const float*)d_in[9];
    const float* Wo = (const float*)d_in[10];
    const float* bo = (const float*)d_in[11];
    float* out = (float*)d_out;

    unsigned short *qh, *ql, *kh, *kl, *vh, *vl;
    unsigned short *Wqh, *Wql, *Wkh, *Wkl, *Wvh, *Wvl, *Woh, *Wol;
    unsigned short *Qh, *Ql, *Kh, *Kl, *Vh, *Vl, *Ch, *Cl;
    cudaGetSymbolAddress((void**)&qh, g_qh);   cudaGetSymbolAddress((void**)&ql, g_ql);
    cudaGetSymbolAddress((void**)&kh, g_kh);   cudaGetSymbolAddress((void**)&kl, g_kl);
    cudaGetSymbolAddress((void**)&vh, g_vh);   cudaGetSymbolAddress((void**)&vl, g_vl);
    cudaGetSymbolAddress((void**)&Wqh, g_Wqh); cudaGetSymbolAddress((void**)&Wql, g_Wql);
    cudaGetSymbolAddress((void**)&Wkh, g_Wkh); cudaGetSymbolAddress((void**)&Wkl, g_Wkl);
    cudaGetSymbolAddress((void**)&Wvh, g_Wvh); cudaGetSymbolAddress((void**)&Wvl, g_Wvl);
    cudaGetSymbolAddress((void**)&Woh, g_Woh); cudaGetSymbolAddress((void**)&Wol, g_Wol);
    cudaGetSymbolAddress((void**)&Qh, g_Qh);   cudaGetSymbolAddress((void**)&Ql, g_Ql);
    cudaGetSymbolAddress((void**)&Kh, g_Kh);   cudaGetSymbolAddress((void**)&Kl, g_Kl);
    cudaGetSymbolAddress((void**)&Vh, g_Vh);   cudaGetSymbolAddress((void**)&Vl, g_Vl);
    cudaGetSymbolAddress((void**)&Ch, g_Ch);   cudaGetSymbolAddress((void**)&Cl, g_Cl);

    cudaFuncSetAttribute(gemm_qkv, cudaFuncAttributeMaxDynamicSharedMemorySize,
                         GM_DSMEM);
    cudaFuncSetAttribute(gemm_out, cudaFuncAttributeMaxDynamicSharedMemorySize,
                         GM_DSMEM);
    cudaFuncSetAttribute(flash_attn_bf16, cudaFuncAttributeMaxDynamicSharedMemorySize,
                         FA_DSMEM);

    const int M = B_ * S_;   // 4096
    const int N = E_;        // 1024
    const int K = E_;        // 1024

    // ---- pre-split inputs + weights (2 fused launches) ----
    const int mn4 = ME_ / 4, wn4 = WE_ / 4;
    dim3 pg3(mn4 / 256, 3);
    presplit3<<<pg3, 256>>>(q, k, v,
                            (unsigned*)qh, (unsigned*)ql, (unsigned*)kh,
                            (unsigned*)kl, (unsigned*)vh, (unsigned*)vl, mn4);
    dim3 pg4(wn4 / 256, 4);
    presplit4<<<pg4, 256>>>(Wq, Wk, Wv, Wo,
                            (unsigned*)Wqh, (unsigned*)Wql, (unsigned*)Wkh,
                            (unsigned*)Wkl, (unsigned*)Wvh, (unsigned*)Wvl,
                            (unsigned*)Woh, (unsigned*)Wol, wn4);

    // ---- fused QKV projections ----
    dim3 qgrid(N / 128, M / 128, 3);
    gemm_qkv<<<qgrid, 256, GM_DSMEM>>>(qh, ql, kh, kl, vh, vl,
                                       Wqh, Wql, Wkh, Wkl, Wvh, Wvl,
                                       bq, bk, bv,
                                       (unsigned*)Qh, (unsigned*)Ql,
                                       (unsigned*)Kh, (unsigned*)Kl,
                                       (unsigned*)Vh, (unsigned*)Vl, M, N, K);

    flash_attn_bf16<<<1024, 128, FA_DSMEM>>>(Qh, Ql, Kh, Kl, Vh, Vl, Ch, Cl);

    dim3 ogrid(N / 128, M / 128);
    gemm_out<<<ogrid, 256, GM_DSMEM>>>(Ch, Cl, Woh, Wol, bo, out, M, N, K);
}